// round 10
// baseline (speedup 1.0000x reference)
#include <cuda_runtime.h>
#include <cuda_fp16.h>
#include <math.h>
#include <stdint.h>

#define BATCH 4
#define C1N 128
#define H1N 128
#define W1N 128
#define C2N 64
#define H2N 64
#define W2N 64
#define LP 4096          // H2*W2 positions / patches
#define KPATCH 576       // C2 * 3 * 3
#define MRAW 2048        // C1 * 4 * 4
#define SCALE_F 10.0f

// ---- scratch (device globals: allocation-free) ----
__device__ __half g_Ah[LP * KPATCH];        // im2col(x2) hi  [p][k]
__device__ __half g_Al[LP * KPATCH];        // im2col(x2) lo
__device__ float  g_invn[LP];
__device__ float  g_mm[LP];
__device__ float  g_S[(size_t)LP * LP];     // fp32 scores  [p][q]
__device__ __half g_P[(size_t)LP * LP];     // softmax out (fp16)  [p][q]
__device__ __half g_rawh[(size_t)MRAW * LP]; // rawT fp16 [m][q]
__device__ float  g_cols[(size_t)MRAW * LP]; // GEMM2 out [m][pos]
__device__ float  g_y[(size_t)BATCH * C1N * H1N * W1N];

// ==================================================================
// mma.sync fp16 + ldmatrix + cp.async (base PTX, compiles at compute_103)
// ==================================================================
__device__ __forceinline__ void mma_f16(float d[4], const uint32_t a[4], const uint32_t b[2]) {
    asm volatile(
        "mma.sync.aligned.m16n8k16.row.col.f32.f16.f16.f32 "
        "{%0,%1,%2,%3},{%4,%5,%6,%7},{%8,%9},{%0,%1,%2,%3};"
        : "+f"(d[0]), "+f"(d[1]), "+f"(d[2]), "+f"(d[3])
        : "r"(a[0]), "r"(a[1]), "r"(a[2]), "r"(a[3]), "r"(b[0]), "r"(b[1]));
}
#define LDSM_X4(R, addr) \
    asm volatile("ldmatrix.sync.aligned.m8n8.x4.shared.b16 {%0,%1,%2,%3}, [%4];" \
        : "=r"((R)[0]), "=r"((R)[1]), "=r"((R)[2]), "=r"((R)[3]) : "r"(addr))

__device__ __forceinline__ uint32_t smem_u32(const void* p) {
    uint32_t a;
    asm("{ .reg .u64 t; cvta.to.shared.u64 t, %1; cvt.u32.u64 %0, t; }" : "=r"(a) : "l"(p));
    return a;
}
__device__ __forceinline__ void cp16(uint32_t dst, const void* src) {
    asm volatile(
        "{ .reg .u64 gp; cvta.to.global.u64 gp, %1;"
        " cp.async.cg.shared.global [%0], [gp], 16; }"
        :: "r"(dst), "l"(src) : "memory");
}
#define CP_COMMIT() asm volatile("cp.async.commit_group;" ::: "memory")
#define CP_WAIT0()  asm volatile("cp.async.wait_group 0;" ::: "memory")

#define SSTR 20    // gemm1 smem row stride in u32 words (16 data + 4 pad)
#define SSTR2 36   // gemm2 smem row stride in u32 words (32 data + 4 pad)
#define STW1 (128 * SSTR)    // words per matrix per stage (gemm1)
#define STW2 (128 * SSTR2)   // words per matrix per stage (gemm2)
#define G1_SMEM (8 * STW1 * 4)   // 4 matrices x 2 stages = 81920 B
#define G2_SMEM (4 * STW2 * 4)   // 2 matrices x 2 stages = 73728 B

// ==================================================================
// GEMM1 (symmetric): S[p][q] = <A_p, A_q> * invn[q].
// Lower-triangle blocks only; writes tile + transpose. fp16 2-term
// split, 3 MMA terms. K=576, BK=32, 8 warps, 128x128 tile, cp.async
// double-buffered. 528 blocks.
// ==================================================================
__global__ void __launch_bounds__(256) gemm1_mma() {
    extern __shared__ uint32_t dsm[];
    const int K = KPATCH;
    int t = threadIdx.x;

    // triangular block decode: bx >= by
    int L = blockIdx.x;
    int bx = (int)((sqrtf(8.f * (float)L + 1.f) - 1.f) * 0.5f);
    while ((bx + 1) * (bx + 2) / 2 <= L) bx++;
    while (bx * (bx + 1) / 2 > L) bx--;
    int by = L - bx * (bx + 1) / 2;

    int m0 = by * 128, n0 = bx * 128;
    int wid = t >> 5, lane = t & 31;
    int wm = (wid >> 1) * 32, wn = (wid & 1) * 64;
    int g = lane >> 2, tig = lane & 3;

    float acc[2][8][4] = {};

    int lm = t >> 1;              // row 0..127
    int lw = (t & 1) * 8;         // u32-word offset within 16-word row
    const __half* pAh = g_Ah + (size_t)(m0 + lm) * K + lw * 2;
    const __half* pAl = g_Al + (size_t)(m0 + lm) * K + lw * 2;
    const __half* pBh = g_Ah + (size_t)(n0 + lm) * K + lw * 2;
    const __half* pBl = g_Al + (size_t)(n0 + lm) * K + lw * 2;

    uint32_t smb = smem_u32(dsm);
    // layout: [Ah s0][Ah s1][Al s0][Al s1][Bh s0][Bh s1][Bl s0][Bl s1]
    uint32_t baseAh = smb;
    uint32_t baseAl = smb + 2 * STW1 * 4;
    uint32_t baseBh = smb + 4 * STW1 * 4;
    uint32_t baseBl = smb + 6 * STW1 * 4;
    uint32_t stOff = (uint32_t)(lm * SSTR + lw) * 4;
    const uint32_t SB = STW1 * 4;   // stage bytes

    // ldmatrix per-lane source rows/column-halves
    int rowA = lane & 15;
    int koffA = ((lane >> 4) & 1) * 4;
    int rowB = (lane & 7) + ((lane & 16) >> 1);
    int koffB = ((lane & 8) >> 1);
    uint32_t aWh = baseAh + 4 * ((wm + rowA) * SSTR + koffA);
    uint32_t aWl = baseAl + 4 * ((wm + rowA) * SSTR + koffA);
    uint32_t bWh = baseBh + 4 * ((wn + rowB) * SSTR + koffB);
    uint32_t bWl = baseBl + 4 * ((wn + rowB) * SSTR + koffB);

    const int NC = K / 32;
    // preload chunk 0 into stage 0
    cp16(baseAh + stOff, pAh);      cp16(baseAh + stOff + 16, pAh + 8);
    cp16(baseAl + stOff, pAl);      cp16(baseAl + stOff + 16, pAl + 8);
    cp16(baseBh + stOff, pBh);      cp16(baseBh + stOff + 16, pBh + 8);
    cp16(baseBl + stOff, pBl);      cp16(baseBl + stOff + 16, pBl + 8);
    CP_COMMIT();

    for (int ci = 0; ci < NC; ci++) {
        CP_WAIT0();
        __syncthreads();
        uint32_t cur = (uint32_t)(ci & 1) * SB;
        if (ci + 1 < NC) {
            uint32_t nxt = (uint32_t)((ci + 1) & 1) * SB;
            int k0 = (ci + 1) * 32;
            cp16(baseAh + nxt + stOff, pAh + k0);
            cp16(baseAh + nxt + stOff + 16, pAh + k0 + 8);
            cp16(baseAl + nxt + stOff, pAl + k0);
            cp16(baseAl + nxt + stOff + 16, pAl + k0 + 8);
            cp16(baseBh + nxt + stOff, pBh + k0);
            cp16(baseBh + nxt + stOff + 16, pBh + k0 + 8);
            cp16(baseBl + nxt + stOff, pBl + k0);
            cp16(baseBl + nxt + stOff + 16, pBl + k0 + 8);
            CP_COMMIT();
        }
#pragma unroll
        for (int s = 0; s < 2; s++) {
            uint32_t ah[2][4], al[2][4], bh[8][2], bl[8][2];
#pragma unroll
            for (int mt = 0; mt < 2; mt++) {
                uint32_t off = cur + (uint32_t)(mt * 16 * SSTR + s * 8) * 4;
                LDSM_X4(ah[mt], aWh + off);
                LDSM_X4(al[mt], aWl + off);
            }
#pragma unroll
            for (int ntp = 0; ntp < 4; ntp++) {
                uint32_t off = cur + (uint32_t)(ntp * 16 * SSTR + s * 8) * 4;
                LDSM_X4(&bh[2 * ntp][0], bWh + off);
                LDSM_X4(&bl[2 * ntp][0], bWl + off);
            }
#pragma unroll
            for (int mt = 0; mt < 2; mt++)
#pragma unroll
                for (int nt = 0; nt < 8; nt++) {
                    mma_f16(acc[mt][nt], ah[mt], bh[nt]);
                    mma_f16(acc[mt][nt], ah[mt], bl[nt]);
                    mma_f16(acc[mt][nt], al[mt], bh[nt]);
                }
        }
    }
    // epilogue: write tile (scale invn[col]) and transpose (scale invn[row])
#pragma unroll
    for (int mt = 0; mt < 2; mt++) {
        int row = m0 + wm + mt * 16 + g;
        float sr0 = __ldg(&g_invn[row]);
        float sr8 = __ldg(&g_invn[row + 8]);
#pragma unroll
        for (int nt = 0; nt < 8; nt++) {
            int col = n0 + wn + nt * 8 + 2 * tig;
            float s0 = __ldg(&g_invn[col]);
            float s1 = __ldg(&g_invn[col + 1]);
            *(float2*)(g_S + (size_t)row * LP + col) =
                make_float2(acc[mt][nt][0] * s0, acc[mt][nt][1] * s1);
            *(float2*)(g_S + (size_t)(row + 8) * LP + col) =
                make_float2(acc[mt][nt][2] * s0, acc[mt][nt][3] * s1);
            g_S[(size_t)col * LP + row]           = acc[mt][nt][0] * sr0;
            g_S[(size_t)(col + 1) * LP + row]     = acc[mt][nt][1] * sr0;
            g_S[(size_t)col * LP + row + 8]       = acc[mt][nt][2] * sr8;
            g_S[(size_t)(col + 1) * LP + row + 8] = acc[mt][nt][3] * sr8;
        }
    }
}

// ==================================================================
// GEMM2: cols[m][p] = sum_q raw[m][q] * P[p][q]
// A = raw fp16, B = P fp16 (1 MMA term). M=2048, N=4096, K=4096,
// BK=64, 8 warps, 128x128 tile, cp.async double-buffered.
// ==================================================================
__global__ void __launch_bounds__(256) gemm2_mma() {
    extern __shared__ uint32_t dsm[];
    int t = threadIdx.x;
    int m0 = blockIdx.y * 128, n0 = blockIdx.x * 128;
    int wid = t >> 5, lane = t & 31;
    int wm = (wid >> 1) * 32, wn = (wid & 1) * 64;
    int g = lane >> 2, tig = lane & 3;

    float acc[2][8][4] = {};

    int lm = t >> 1;
    int lw = (t & 1) * 16;        // u32-word offset (half of 32-word row)
    const __half* pA = g_rawh + (size_t)(m0 + lm) * LP + lw * 2;
    const __half* pB = g_P    + (size_t)(n0 + lm) * LP + lw * 2;

    uint32_t smb = smem_u32(dsm);
    // layout: [A s0][A s1][B s0][B s1]
    uint32_t baseA = smb;
    uint32_t baseB = smb + 2 * STW2 * 4;
    uint32_t stOff = (uint32_t)(lm * SSTR2 + lw) * 4;
    const uint32_t SB = STW2 * 4;

    int rowA = lane & 15;
    int koffA = ((lane >> 4) & 1) * 4;
    int rowB = (lane & 7) + ((lane & 16) >> 1);
    int koffB = ((lane & 8) >> 1);
    uint32_t aW = baseA + 4 * ((wm + rowA) * SSTR2 + koffA);
    uint32_t bW = baseB + 4 * ((wn + rowB) * SSTR2 + koffB);

    const int NC = LP / 64;
    // preload chunk 0 into stage 0
#pragma unroll
    for (int j = 0; j < 4; j++) {
        cp16(baseA + stOff + j * 16, pA + j * 8);
        cp16(baseB + stOff + j * 16, pB + j * 8);
    }
    CP_COMMIT();

    for (int ci = 0; ci < NC; ci++) {
        CP_WAIT0();
        __syncthreads();
        uint32_t cur = (uint32_t)(ci & 1) * SB;
        if (ci + 1 < NC) {
            uint32_t nxt = (uint32_t)((ci + 1) & 1) * SB;
            int k0 = (ci + 1) * 64;
#pragma unroll
            for (int j = 0; j < 4; j++) {
                cp16(baseA + nxt + stOff + j * 16, pA + k0 + j * 8);
                cp16(baseB + nxt + stOff + j * 16, pB + k0 + j * 8);
            }
            CP_COMMIT();
        }
#pragma unroll
        for (int s = 0; s < 4; s++) {
            uint32_t a[2][4], b[8][2];
#pragma unroll
            for (int mt = 0; mt < 2; mt++) {
                uint32_t off = cur + (uint32_t)(mt * 16 * SSTR2 + s * 8) * 4;
                LDSM_X4(a[mt], aW + off);
            }
#pragma unroll
            for (int ntp = 0; ntp < 4; ntp++) {
                uint32_t off = cur + (uint32_t)(ntp * 16 * SSTR2 + s * 8) * 4;
                LDSM_X4(&b[2 * ntp][0], bW + off);
            }
#pragma unroll
            for (int mt = 0; mt < 2; mt++)
#pragma unroll
                for (int nt = 0; nt < 8; nt++)
                    mma_f16(acc[mt][nt], a[mt], b[nt]);
        }
    }
#pragma unroll
    for (int mt = 0; mt < 2; mt++) {
        int row = m0 + wm + mt * 16 + g;
#pragma unroll
        for (int nt = 0; nt < 8; nt++) {
            int col = n0 + wn + nt * 8 + 2 * tig;
            *(float2*)(g_cols + (size_t)row * LP + col) =
                make_float2(acc[mt][nt][0], acc[mt][nt][1]);
            *(float2*)(g_cols + (size_t)(row + 8) * LP + col) =
                make_float2(acc[mt][nt][2], acc[mt][nt][3]);
        }
    }
}

// ------------------------------------------------------------------
// im2col of x2 (k=3,s=1,pad=1) -> fp16 hi/lo split + inverse norms
// ------------------------------------------------------------------
__global__ void im2col_norm_kernel(const float* __restrict__ x2) {
    int p = blockIdx.x;
    int pi = p >> 6, pj = p & 63;
    int tid = threadIdx.x;
    float ss = 0.f;
    for (int k = tid; k < KPATCH; k += 256) {
        int c = k / 9, ki = k % 9;
        int ky = ki / 3, kx = ki % 3;
        int yy = pi - 1 + ky, xx = pj - 1 + kx;
        float v = 0.f;
        if (yy >= 0 && yy < H2N && xx >= 0 && xx < W2N)
            v = x2[(c * H2N + yy) * W2N + xx];
        __half h = __float2half_rn(v);
        g_Ah[p * KPATCH + k] = h;
        g_Al[p * KPATCH + k] = __float2half_rn(v - __half2float(h));
        ss += v * v;
    }
    __shared__ float red[256];
    red[tid] = ss;
    __syncthreads();
    for (int s = 128; s > 0; s >>= 1) {
        if (tid < s) red[tid] += red[tid + s];
        __syncthreads();
    }
    if (tid == 0) {
        float n = sqrtf(red[0]);
        g_invn[p] = 1.f / fmaxf(n, 1e-4f);
    }
}

// ------------------------------------------------------------------
// mask patches (k=4,s=2,pad=1): mm[q] = (sum == 0) ? 1 : 0
// ------------------------------------------------------------------
__global__ void mask_patch_kernel(const float* __restrict__ mask) {
    int q = blockIdx.x * blockDim.x + threadIdx.x;
    if (q >= LP) return;
    int qi = q >> 6, qj = q & 63;
    float s = 0.f;
    for (int ky = 0; ky < 4; ky++)
        for (int kx = 0; kx < 4; kx++) {
            int yy = 2 * qi - 1 + ky, xx = 2 * qj - 1 + kx;
            if (yy >= 0 && yy < H1N && xx >= 0 && xx < W1N)
                s += mask[yy * W1N + xx];
        }
    g_mm[q] = (s == 0.f) ? 1.f : 0.f;
}

// ------------------------------------------------------------------
// masked softmax over q for each row p; writes fp16 P
// ------------------------------------------------------------------
__global__ void __launch_bounds__(256) softmax_kernel(const float* __restrict__ mask_all) {
    int p = blockIdx.x;
    int tid = threadIdx.x;
    float map = mask_all[p];
    const float* row = g_S + (size_t)p * LP;
    __half* prow = g_P + (size_t)p * LP;

    float v[16];
    float lmax = -1e30f;
#pragma unroll
    for (int i = 0; i < 16; i++) {
        int q = tid + i * 256;
        float x = row[q] * g_mm[q] * map;
        v[i] = x;
        lmax = fmaxf(lmax, x);
    }
    __shared__ float red[256];
    red[tid] = lmax;
    __syncthreads();
    for (int s = 128; s > 0; s >>= 1) {
        if (tid < s) red[tid] = fmaxf(red[tid], red[tid + s]);
        __syncthreads();
    }
    float gmax = red[0];
    __syncthreads();

    float lsum = 0.f;
#pragma unroll
    for (int i = 0; i < 16; i++) {
        float e = expf(SCALE_F * (v[i] - gmax));
        v[i] = e;
        lsum += e;
    }
    red[tid] = lsum;
    __syncthreads();
    for (int s = 128; s > 0; s >>= 1) {
        if (tid < s) red[tid] += red[tid + s];
        __syncthreads();
    }
    float inv = 1.f / red[0];
#pragma unroll
    for (int i = 0; i < 16; i++) {
        int q = tid + i * 256;
        float pv = fmaxf(v[i] * inv * g_mm[q] * map, 1e-8f);
        prow[q] = __float2half_rn(pv);
    }
}

// ------------------------------------------------------------------
// rawT[m][q] -> fp16 (k=4, s=2, pad=1), m = o*16+ky*4+kx
// ------------------------------------------------------------------
__global__ void fill_raw_kernel(const float* __restrict__ x1) {
    int q = blockIdx.x * blockDim.x + threadIdx.x;
    int m = blockIdx.y;
    int o = m >> 4, kk = m & 15;
    int ky = kk >> 2, kx = kk & 3;
    int qi = q >> 6, qj = q & 63;
    int yy = 2 * qi - 1 + ky, xx = 2 * qj - 1 + kx;
    float v = 0.f;
    if (yy >= 0 && yy < H1N && xx >= 0 && xx < W1N)
        v = x1[(o * H1N + yy) * W1N + xx];
    g_rawh[(size_t)m * LP + q] = __float2half_rn(v);
}

// ------------------------------------------------------------------
// col2im gather: y[o,Y,X] = 0.25 * sum over <=4 entries of g_cols
// ------------------------------------------------------------------
__global__ void col2im_kernel(int b) {
    int idx = blockIdx.x * blockDim.x + threadIdx.x;
    int X = idx & 127;
    int Y = (idx >> 7) & 127;
    int o = idx >> 14;
    float acc = 0.f;
    int ky0 = (Y & 1) ? 0 : 1;
    int kx0 = (X & 1) ? 0 : 1;
#pragma unroll
    for (int t = 0; t < 2; t++) {
        int ky = ky0 + 2 * t;
        int i = (Y + 1 - ky) >> 1;
        if (i < 0 || i >= 64) continue;
#pragma unroll
        for (int u = 0; u < 2; u++) {
            int kx = kx0 + 2 * u;
            int j = (X + 1 - kx) >> 1;
            if (j < 0 || j >= 64) continue;
            acc += g_cols[(size_t)(o * 16 + ky * 4 + kx) * LP + i * 64 + j];
        }
    }
    g_y[(size_t)b * C1N * H1N * W1N + idx] = acc * 0.25f;
}

// ------------------------------------------------------------------
// final: 4 grouped dilated 3x3 convs (rates 1,2,4,8) + bias + relu
// ------------------------------------------------------------------
__global__ void __launch_bounds__(256) final_conv_kernel(
    const float* __restrict__ w, const float* __restrict__ bias, float* __restrict__ out)
{
    int tile = blockIdx.x;
    int g = blockIdx.y;
    int b = blockIdx.z;
    int r = 1 << g;  // rates 1,2,4,8
    int ty0 = (tile >> 3) * 16, tx0 = (tile & 7) * 16;
    int HW = 16 + 2 * r;
    __shared__ float yt[32 * 32];
    __shared__ float ws[144];
    int tid = threadIdx.x;
    int py = tid >> 4, px = tid & 15;

    float acc[16];
#pragma unroll
    for (int i = 0; i < 16; i++) acc[i] = 0.f;

    const float* yb = g_y + (size_t)b * C1N * H1N * W1N;
    for (int c = 0; c < C1N; c++) {
        for (int idx = tid; idx < HW * HW; idx += 256) {
            int iy = idx / HW, ix = idx % HW;
            int gy = ty0 - r + iy, gx = tx0 - r + ix;
            float v = 0.f;
            if (gy >= 0 && gy < H1N && gx >= 0 && gx < W1N)
                v = yb[(c * H1N + gy) * W1N + gx];
            yt[idx] = v;
        }
        if (tid < 144)
            ws[tid] = w[((g * 16 + tid / 9) * C1N + c) * 9 + tid % 9];
        __syncthreads();
#pragma unroll
        for (int ky = 0; ky < 3; ky++)
#pragma unroll
            for (int kx = 0; kx < 3; kx++) {
                float v = yt[(py + ky * r) * HW + px + kx * r];
#pragma unroll
                for (int oc = 0; oc < 16; oc++)
                    acc[oc] += v * ws[oc * 9 + ky * 3 + kx];
            }
        __syncthreads();
    }
    int Y = ty0 + py, X = tx0 + px;
#pragma unroll
    for (int oc = 0; oc < 16; oc++) {
        float o = acc[oc] + bias[g * 16 + oc];
        out[((size_t)(b * 64 + g * 16 + oc) * H1N + Y) * W1N + X] = fmaxf(o, 0.f);
    }
}

// ------------------------------------------------------------------
extern "C" void kernel_launch(void* const* d_in, const int* in_sizes, int n_in,
                              void* d_out, int out_size) {
    const float* x1       = (const float*)d_in[0];  // [4,128,128,128]
    const float* x2       = (const float*)d_in[1];  // [4,64,64,64]
    const float* mask     = (const float*)d_in[2];  // [4,1,128,128]
    const float* mask_all = (const float*)d_in[3];  // [4,1,64,64]
    const float* conv_w   = (const float*)d_in[4];  // [4,16,128,3,3]
    const float* conv_b   = (const float*)d_in[5];  // [4,16]
    float* out = (float*)d_out;

    static int attr_done = 0;
    if (!attr_done) {
        cudaFuncSetAttribute(gemm1_mma, cudaFuncAttributeMaxDynamicSharedMemorySize, G1_SMEM);
        cudaFuncSetAttribute(gemm2_mma, cudaFuncAttributeMaxDynamicSharedMemorySize, G2_SMEM);
        attr_done = 1;
    }

    for (int b = 0; b < BATCH; b++) {
        im2col_norm_kernel<<<LP, 256>>>(x2 + (size_t)b * C2N * H2N * W2N);
        mask_patch_kernel<<<LP / 256, 256>>>(mask + (size_t)b * H1N * W1N);
        gemm1_mma<<<528, 256, G1_SMEM>>>();
        softmax_kernel<<<LP, 256>>>(mask_all + (size_t)b * LP);
        fill_raw_kernel<<<dim3(LP / 256, MRAW), 256>>>(x1 + (size_t)b * C1N * H1N * W1N);
        gemm2_mma<<<dim3(32, 16), 256, G2_SMEM>>>();
        col2im_kernel<<<(C1N * H1N * W1N) / 256, 256>>>(b);
    }
    final_conv_kernel<<<dim3(64, 4, 4), 256>>>(conv_w, conv_b, out);
}

// round 11
// speedup vs baseline: 1.0685x; 1.0685x over previous
#include <cuda_runtime.h>
#include <cuda_fp16.h>
#include <math.h>
#include <stdint.h>

#define BATCH 4
#define C1N 128
#define H1N 128
#define W1N 128
#define C2N 64
#define H2N 64
#define W2N 64
#define LP 4096          // H2*W2 positions / patches
#define KPATCH 576       // C2 * 3 * 3
#define MRAW 2048        // C1 * 4 * 4
#define SCALE_F 10.0f

// ---- scratch (device globals: allocation-free) ----
__device__ __half g_Ah[LP * KPATCH];        // im2col(x2) hi  [p][k]
__device__ __half g_Al[LP * KPATCH];        // im2col(x2) lo
__device__ float  g_invn[LP];
__device__ float  g_mm[LP];
__device__ float  g_S[(size_t)LP * LP];     // fp32 scores  [p][q]
__device__ __half g_P[(size_t)LP * LP];     // softmax out (fp16)  [p][q]
__device__ __half g_rawh[(size_t)MRAW * LP]; // rawT fp16 [m][q]
__device__ float  g_cols[(size_t)MRAW * LP]; // GEMM2 out [m][pos]
__device__ float  g_y[(size_t)BATCH * C1N * H1N * W1N];

// ==================================================================
// mma.sync fp16 + ldmatrix (base PTX, compiles at compute_103)
// ==================================================================
__device__ __forceinline__ void mma_f16(float d[4], const uint32_t a[4], const uint32_t b[2]) {
    asm volatile(
        "mma.sync.aligned.m16n8k16.row.col.f32.f16.f16.f32 "
        "{%0,%1,%2,%3},{%4,%5,%6,%7},{%8,%9},{%0,%1,%2,%3};"
        : "+f"(d[0]), "+f"(d[1]), "+f"(d[2]), "+f"(d[3])
        : "r"(a[0]), "r"(a[1]), "r"(a[2]), "r"(a[3]), "r"(b[0]), "r"(b[1]));
}
#define LDSM_X4(R, addr) \
    asm volatile("ldmatrix.sync.aligned.m8n8.x4.shared.b16 {%0,%1,%2,%3}, [%4];" \
        : "=r"((R)[0]), "=r"((R)[1]), "=r"((R)[2]), "=r"((R)[3]) : "r"(addr))

__device__ __forceinline__ uint32_t smem_u32(const void* p) {
    uint32_t a;
    asm("{ .reg .u64 t; cvta.to.shared.u64 t, %1; cvt.u32.u64 %0, t; }" : "=r"(a) : "l"(p));
    return a;
}

#define SSTR 20    // gemm1 smem row stride in u32 words (16 data + 4 pad)
#define SSTR2 36   // gemm2 smem row stride in u32 words (32 data + 4 pad)

// ==================================================================
// GEMM1 (symmetric): S[p][q] = <A_p, A_q> * invn[q].
// Lower-triangle blocks only; writes tile + transpose. fp16 2-term
// split, 3 MMA terms. K=576, BK=32, 8 warps, 128x128 tile. 528 blocks.
// ==================================================================
__global__ void __launch_bounds__(256) gemm1_mma() {
    __shared__ uint32_t sAh[128 * SSTR], sAl[128 * SSTR];
    __shared__ uint32_t sBh[128 * SSTR], sBl[128 * SSTR];
    const int K = KPATCH;
    int t = threadIdx.x;

    // triangular block decode: bx >= by
    int L = blockIdx.x;
    int bx = (int)((sqrtf(8.f * (float)L + 1.f) - 1.f) * 0.5f);
    while ((bx + 1) * (bx + 2) / 2 <= L) bx++;
    while (bx * (bx + 1) / 2 > L) bx--;
    int by = L - bx * (bx + 1) / 2;

    int m0 = by * 128, n0 = bx * 128;
    int wid = t >> 5, lane = t & 31;
    int wm = (wid >> 1) * 32, wn = (wid & 1) * 64;
    int g = lane >> 2, tig = lane & 3;

    float acc[2][8][4] = {};

    int lm = t >> 1;              // row 0..127
    int lw = (t & 1) * 8;         // u32-word offset within 16-word row
    int sbase = lm * SSTR + lw;
    const __half* pAh = g_Ah + (size_t)(m0 + lm) * K + lw * 2;
    const __half* pAl = g_Al + (size_t)(m0 + lm) * K + lw * 2;
    const __half* pBh = g_Ah + (size_t)(n0 + lm) * K + lw * 2;
    const __half* pBl = g_Al + (size_t)(n0 + lm) * K + lw * 2;

    // ldmatrix per-lane source rows/column-halves
    int rowA = lane & 15;
    int koffA = ((lane >> 4) & 1) * 4;
    int rowB = (lane & 7) + ((lane & 16) >> 1);
    int koffB = ((lane & 8) >> 1);
    uint32_t aWh = smem_u32(sAh) + 4 * ((wm + rowA) * SSTR + koffA);
    uint32_t aWl = smem_u32(sAl) + 4 * ((wm + rowA) * SSTR + koffA);
    uint32_t bWh = smem_u32(sBh) + 4 * ((wn + rowB) * SSTR + koffB);
    uint32_t bWl = smem_u32(sBl) + 4 * ((wn + rowB) * SSTR + koffB);

    const int NC = K / 32;
    uint4 vah = *(const uint4*)pAh;
    uint4 vah2 = *(const uint4*)(pAh + 8);
    uint4 val_ = *(const uint4*)pAl;
    uint4 val2 = *(const uint4*)(pAl + 8);
    uint4 vbh = *(const uint4*)pBh;
    uint4 vbh2 = *(const uint4*)(pBh + 8);
    uint4 vbl = *(const uint4*)pBl;
    uint4 vbl2 = *(const uint4*)(pBl + 8);

    for (int ci = 0; ci < NC; ci++) {
        if (ci > 0) __syncthreads();
        *(uint4*)&sAh[sbase] = vah;  *(uint4*)&sAh[sbase + 4] = vah2;
        *(uint4*)&sAl[sbase] = val_; *(uint4*)&sAl[sbase + 4] = val2;
        *(uint4*)&sBh[sbase] = vbh;  *(uint4*)&sBh[sbase + 4] = vbh2;
        *(uint4*)&sBl[sbase] = vbl;  *(uint4*)&sBl[sbase + 4] = vbl2;
        __syncthreads();
        if (ci + 1 < NC) {
            int k0 = (ci + 1) * 32;
            vah = *(const uint4*)(pAh + k0);
            vah2 = *(const uint4*)(pAh + k0 + 8);
            val_ = *(const uint4*)(pAl + k0);
            val2 = *(const uint4*)(pAl + k0 + 8);
            vbh = *(const uint4*)(pBh + k0);
            vbh2 = *(const uint4*)(pBh + k0 + 8);
            vbl = *(const uint4*)(pBl + k0);
            vbl2 = *(const uint4*)(pBl + k0 + 8);
        }
#pragma unroll
        for (int s = 0; s < 2; s++) {
            uint32_t ah[2][4], al[2][4], bh[8][2], bl[8][2];
#pragma unroll
            for (int mt = 0; mt < 2; mt++) {
                uint32_t off = (uint32_t)(mt * 16 * SSTR + s * 8) * 4;
                LDSM_X4(ah[mt], aWh + off);
                LDSM_X4(al[mt], aWl + off);
            }
#pragma unroll
            for (int ntp = 0; ntp < 4; ntp++) {
                uint32_t off = (uint32_t)(ntp * 16 * SSTR + s * 8) * 4;
                LDSM_X4(&bh[2 * ntp][0], bWh + off);
                LDSM_X4(&bl[2 * ntp][0], bWl + off);
            }
#pragma unroll
            for (int mt = 0; mt < 2; mt++)
#pragma unroll
                for (int nt = 0; nt < 8; nt++) {
                    mma_f16(acc[mt][nt], ah[mt], bh[nt]);
                    mma_f16(acc[mt][nt], ah[mt], bl[nt]);
                    mma_f16(acc[mt][nt], al[mt], bh[nt]);
                }
        }
    }
    // epilogue: write tile (scale invn[col]) and transpose (scale invn[row])
#pragma unroll
    for (int mt = 0; mt < 2; mt++) {
        int row = m0 + wm + mt * 16 + g;
        float sr0 = __ldg(&g_invn[row]);
        float sr8 = __ldg(&g_invn[row + 8]);
#pragma unroll
        for (int nt = 0; nt < 8; nt++) {
            int col = n0 + wn + nt * 8 + 2 * tig;
            float s0 = __ldg(&g_invn[col]);
            float s1 = __ldg(&g_invn[col + 1]);
            *(float2*)(g_S + (size_t)row * LP + col) =
                make_float2(acc[mt][nt][0] * s0, acc[mt][nt][1] * s1);
            *(float2*)(g_S + (size_t)(row + 8) * LP + col) =
                make_float2(acc[mt][nt][2] * s0, acc[mt][nt][3] * s1);
            g_S[(size_t)col * LP + row]           = acc[mt][nt][0] * sr0;
            g_S[(size_t)(col + 1) * LP + row]     = acc[mt][nt][1] * sr0;
            g_S[(size_t)col * LP + row + 8]       = acc[mt][nt][2] * sr8;
            g_S[(size_t)(col + 1) * LP + row + 8] = acc[mt][nt][3] * sr8;
        }
    }
}

// ==================================================================
// GEMM2: cols[m][p] = sum_q raw[m][q] * P[p][q]
// A = raw single fp16, B = P single fp16 (1 MMA term).
// M=2048, N=4096, K=4096, BK=64, 8 warps, 128x128 tile.
// ==================================================================
__global__ void __launch_bounds__(256) gemm2_mma() {
    __shared__ uint32_t sA[128 * SSTR2];
    __shared__ uint32_t sB[128 * SSTR2];
    int t = threadIdx.x;
    int m0 = blockIdx.y * 128, n0 = blockIdx.x * 128;
    int wid = t >> 5, lane = t & 31;
    int wm = (wid >> 1) * 32, wn = (wid & 1) * 64;
    int g = lane >> 2, tig = lane & 3;

    float acc[2][8][4] = {};

    int lm = t >> 1;
    int lw = (t & 1) * 16;        // u32-word offset (half of 32-word row)
    int sbase = lm * SSTR2 + lw;
    const __half* pA = g_rawh + (size_t)(m0 + lm) * LP + lw * 2;
    const __half* pB = g_P    + (size_t)(n0 + lm) * LP + lw * 2;

    int rowA = lane & 15;
    int koffA = ((lane >> 4) & 1) * 4;
    int rowB = (lane & 7) + ((lane & 16) >> 1);
    int koffB = ((lane & 8) >> 1);
    uint32_t aW = smem_u32(sA) + 4 * ((wm + rowA) * SSTR2 + koffA);
    uint32_t bW = smem_u32(sB) + 4 * ((wn + rowB) * SSTR2 + koffB);

    const int NC = LP / 64;
    uint4 va[4], vb[4];
#pragma unroll
    for (int j = 0; j < 4; j++) {
        va[j] = *(const uint4*)(pA + j * 8);
        vb[j] = *(const uint4*)(pB + j * 8);
    }

    for (int ci = 0; ci < NC; ci++) {
        if (ci > 0) __syncthreads();
#pragma unroll
        for (int j = 0; j < 4; j++) {
            *(uint4*)&sA[sbase + j * 4] = va[j];
            *(uint4*)&sB[sbase + j * 4] = vb[j];
        }
        __syncthreads();
        if (ci + 1 < NC) {
            int k0 = (ci + 1) * 64;
#pragma unroll
            for (int j = 0; j < 4; j++) {
                va[j] = *(const uint4*)(pA + k0 + j * 8);
                vb[j] = *(const uint4*)(pB + k0 + j * 8);
            }
        }
#pragma unroll
        for (int s = 0; s < 4; s++) {
            uint32_t a[2][4], b[8][2];
#pragma unroll
            for (int mt = 0; mt < 2; mt++) {
                uint32_t off = (uint32_t)(mt * 16 * SSTR2 + s * 8) * 4;
                LDSM_X4(a[mt], aW + off);
            }
#pragma unroll
            for (int ntp = 0; ntp < 4; ntp++) {
                uint32_t off = (uint32_t)(ntp * 16 * SSTR2 + s * 8) * 4;
                LDSM_X4(&b[2 * ntp][0], bW + off);
            }
#pragma unroll
            for (int mt = 0; mt < 2; mt++)
#pragma unroll
                for (int nt = 0; nt < 8; nt++)
                    mma_f16(acc[mt][nt], a[mt], b[nt]);
        }
    }
#pragma unroll
    for (int mt = 0; mt < 2; mt++) {
        int row = m0 + wm + mt * 16 + g;
#pragma unroll
        for (int nt = 0; nt < 8; nt++) {
            int col = n0 + wn + nt * 8 + 2 * tig;
            *(float2*)(g_cols + (size_t)row * LP + col) =
                make_float2(acc[mt][nt][0], acc[mt][nt][1]);
            *(float2*)(g_cols + (size_t)(row + 8) * LP + col) =
                make_float2(acc[mt][nt][2], acc[mt][nt][3]);
        }
    }
}

// ------------------------------------------------------------------
// im2col of x2 (k=3,s=1,pad=1) -> fp16 hi/lo split + inverse norms
// ------------------------------------------------------------------
__global__ void im2col_norm_kernel(const float* __restrict__ x2) {
    int p = blockIdx.x;
    int pi = p >> 6, pj = p & 63;
    int tid = threadIdx.x;
    float ss = 0.f;
    for (int k = tid; k < KPATCH; k += 256) {
        int c = k / 9, ki = k % 9;
        int ky = ki / 3, kx = ki % 3;
        int yy = pi - 1 + ky, xx = pj - 1 + kx;
        float v = 0.f;
        if (yy >= 0 && yy < H2N && xx >= 0 && xx < W2N)
            v = x2[(c * H2N + yy) * W2N + xx];
        __half h = __float2half_rn(v);
        g_Ah[p * KPATCH + k] = h;
        g_Al[p * KPATCH + k] = __float2half_rn(v - __half2float(h));
        ss += v * v;
    }
    __shared__ float red[256];
    red[tid] = ss;
    __syncthreads();
    for (int s = 128; s > 0; s >>= 1) {
        if (tid < s) red[tid] += red[tid + s];
        __syncthreads();
    }
    if (tid == 0) {
        float n = sqrtf(red[0]);
        g_invn[p] = 1.f / fmaxf(n, 1e-4f);
    }
}

// ------------------------------------------------------------------
// mask patches (k=4,s=2,pad=1): mm[q] = (sum == 0) ? 1 : 0
// ------------------------------------------------------------------
__global__ void mask_patch_kernel(const float* __restrict__ mask) {
    int q = blockIdx.x * blockDim.x + threadIdx.x;
    if (q >= LP) return;
    int qi = q >> 6, qj = q & 63;
    float s = 0.f;
    for (int ky = 0; ky < 4; ky++)
        for (int kx = 0; kx < 4; kx++) {
            int yy = 2 * qi - 1 + ky, xx = 2 * qj - 1 + kx;
            if (yy >= 0 && yy < H1N && xx >= 0 && xx < W1N)
                s += mask[yy * W1N + xx];
        }
    g_mm[q] = (s == 0.f) ? 1.f : 0.f;
}

// ------------------------------------------------------------------
// masked softmax over q for each row p; writes fp16 P
// ------------------------------------------------------------------
__global__ void __launch_bounds__(256) softmax_kernel(const float* __restrict__ mask_all) {
    int p = blockIdx.x;
    int tid = threadIdx.x;
    float map = mask_all[p];
    const float* row = g_S + (size_t)p * LP;
    __half* prow = g_P + (size_t)p * LP;

    float v[16];
    float lmax = -1e30f;
#pragma unroll
    for (int i = 0; i < 16; i++) {
        int q = tid + i * 256;
        float x = row[q] * g_mm[q] * map;
        v[i] = x;
        lmax = fmaxf(lmax, x);
    }
    __shared__ float red[256];
    red[tid] = lmax;
    __syncthreads();
    for (int s = 128; s > 0; s >>= 1) {
        if (tid < s) red[tid] = fmaxf(red[tid], red[tid + s]);
        __syncthreads();
    }
    float gmax = red[0];
    __syncthreads();

    float lsum = 0.f;
#pragma unroll
    for (int i = 0; i < 16; i++) {
        float e = expf(SCALE_F * (v[i] - gmax));
        v[i] = e;
        lsum += e;
    }
    red[tid] = lsum;
    __syncthreads();
    for (int s = 128; s > 0; s >>= 1) {
        if (tid < s) red[tid] += red[tid + s];
        __syncthreads();
    }
    float inv = 1.f / red[0];
#pragma unroll
    for (int i = 0; i < 16; i++) {
        int q = tid + i * 256;
        float pv = fmaxf(v[i] * inv * g_mm[q] * map, 1e-8f);
        prow[q] = __float2half_rn(pv);
    }
}

// ------------------------------------------------------------------
// rawT[m][q] -> fp16 (k=4, s=2, pad=1), m = o*16+ky*4+kx
// ------------------------------------------------------------------
__global__ void fill_raw_kernel(const float* __restrict__ x1) {
    int q = blockIdx.x * blockDim.x + threadIdx.x;
    int m = blockIdx.y;
    int o = m >> 4, kk = m & 15;
    int ky = kk >> 2, kx = kk & 3;
    int qi = q >> 6, qj = q & 63;
    int yy = 2 * qi - 1 + ky, xx = 2 * qj - 1 + kx;
    float v = 0.f;
    if (yy >= 0 && yy < H1N && xx >= 0 && xx < W1N)
        v = x1[(o * H1N + yy) * W1N + xx];
    g_rawh[(size_t)m * LP + q] = __float2half_rn(v);
}

// ------------------------------------------------------------------
// col2im gather: y[o,Y,X] = 0.25 * sum over <=4 entries of g_cols
// ------------------------------------------------------------------
__global__ void col2im_kernel(int b) {
    int idx = blockIdx.x * blockDim.x + threadIdx.x;
    int X = idx & 127;
    int Y = (idx >> 7) & 127;
    int o = idx >> 14;
    float acc = 0.f;
    int ky0 = (Y & 1) ? 0 : 1;
    int kx0 = (X & 1) ? 0 : 1;
#pragma unroll
    for (int t = 0; t < 2; t++) {
        int ky = ky0 + 2 * t;
        int i = (Y + 1 - ky) >> 1;
        if (i < 0 || i >= 64) continue;
#pragma unroll
        for (int u = 0; u < 2; u++) {
            int kx = kx0 + 2 * u;
            int j = (X + 1 - kx) >> 1;
            if (j < 0 || j >= 64) continue;
            acc += g_cols[(size_t)(o * 16 + ky * 4 + kx) * LP + i * 64 + j];
        }
    }
    g_y[(size_t)b * C1N * H1N * W1N + idx] = acc * 0.25f;
}

// ------------------------------------------------------------------
// final: 4 grouped dilated 3x3 convs (rates 1,2,4,8) + bias + relu
// ------------------------------------------------------------------
__global__ void __launch_bounds__(256) final_conv_kernel(
    const float* __restrict__ w, const float* __restrict__ bias, float* __restrict__ out)
{
    int tile = blockIdx.x;
    int g = blockIdx.y;
    int b = blockIdx.z;
    int r = 1 << g;  // rates 1,2,4,8
    int ty0 = (tile >> 3) * 16, tx0 = (tile & 7) * 16;
    int HW = 16 + 2 * r;
    __shared__ float yt[32 * 32];
    __shared__ float ws[144];
    int tid = threadIdx.x;
    int py = tid >> 4, px = tid & 15;

    float acc[16];
#pragma unroll
    for (int i = 0; i < 16; i++) acc[i] = 0.f;

    const float* yb = g_y + (size_t)b * C1N * H1N * W1N;
    for (int c = 0; c < C1N; c++) {
        for (int idx = tid; idx < HW * HW; idx += 256) {
            int iy = idx / HW, ix = idx % HW;
            int gy = ty0 - r + iy, gx = tx0 - r + ix;
            float v = 0.f;
            if (gy >= 0 && gy < H1N && gx >= 0 && gx < W1N)
                v = yb[(c * H1N + gy) * W1N + gx];
            yt[idx] = v;
        }
        if (tid < 144)
            ws[tid] = w[((g * 16 + tid / 9) * C1N + c) * 9 + tid % 9];
        __syncthreads();
#pragma unroll
        for (int ky = 0; ky < 3; ky++)
#pragma unroll
            for (int kx = 0; kx < 3; kx++) {
                float v = yt[(py + ky * r) * HW + px + kx * r];
#pragma unroll
                for (int oc = 0; oc < 16; oc++)
                    acc[oc] += v * ws[oc * 9 + ky * 3 + kx];
            }
        __syncthreads();
    }
    int Y = ty0 + py, X = tx0 + px;
#pragma unroll
    for (int oc = 0; oc < 16; oc++) {
        float o = acc[oc] + bias[g * 16 + oc];
        out[((size_t)(b * 64 + g * 16 + oc) * H1N + Y) * W1N + X] = fmaxf(o, 0.f);
    }
}

// ------------------------------------------------------------------
extern "C" void kernel_launch(void* const* d_in, const int* in_sizes, int n_in,
                              void* d_out, int out_size) {
    const float* x1       = (const float*)d_in[0];  // [4,128,128,128]
    const float* x2       = (const float*)d_in[1];  // [4,64,64,64]
    const float* mask     = (const float*)d_in[2];  // [4,1,128,128]
    const float* mask_all = (const float*)d_in[3];  // [4,1,64,64]
    const float* conv_w   = (const float*)d_in[4];  // [4,16,128,3,3]
    const float* conv_b   = (const float*)d_in[5];  // [4,16]
    float* out = (float*)d_out;

    static cudaStream_t s2 = nullptr;
    static cudaEvent_t evFork[BATCH], evJoin[BATCH];
    if (!s2) {
        cudaStreamCreateWithFlags(&s2, cudaStreamNonBlocking);
        for (int b = 0; b < BATCH; b++) {
            cudaEventCreateWithFlags(&evFork[b], cudaEventDisableTiming);
            cudaEventCreateWithFlags(&evJoin[b], cudaEventDisableTiming);
        }
    }

    for (int b = 0; b < BATCH; b++) {
        // fork: mask_patch + fill_raw run on s2, overlapped with im2col+gemm1
        cudaEventRecord(evFork[b], 0);
        cudaStreamWaitEvent(s2, evFork[b], 0);
        mask_patch_kernel<<<LP / 256, 256, 0, s2>>>(mask + (size_t)b * H1N * W1N);
        fill_raw_kernel<<<dim3(LP / 256, MRAW), 256, 0, s2>>>(x1 + (size_t)b * C1N * H1N * W1N);
        cudaEventRecord(evJoin[b], s2);

        im2col_norm_kernel<<<LP, 256>>>(x2 + (size_t)b * C2N * H2N * W2N);
        gemm1_mma<<<528, 256>>>();
        // join before softmax (needs g_mm); gemm2 (needs g_rawh) is later
        cudaStreamWaitEvent(0, evJoin[b], 0);
        softmax_kernel<<<LP, 256>>>(mask_all + (size_t)b * LP);
        gemm2_mma<<<dim3(32, 16), 256>>>();
        col2im_kernel<<<(C1N * H1N * W1N) / 256, 256>>>(b);
    }
    final_conv_kernel<<<dim3(64, 4, 4), 256>>>(conv_w, conv_b, out);
}

// round 12
// speedup vs baseline: 1.0881x; 1.0183x over previous
#include <cuda_runtime.h>
#include <cuda_fp16.h>
#include <math.h>
#include <stdint.h>

#define BATCH 4
#define C1N 128
#define H1N 128
#define W1N 128
#define C2N 64
#define H2N 64
#define W2N 64
#define LP 4096          // H2*W2 positions / patches
#define KPATCH 576       // C2 * 3 * 3
#define MRAW 2048        // C1 * 4 * 4
#define SCALE_F 10.0f

// ---- scratch (device globals: allocation-free) ----
__device__ __half g_Ah[LP * KPATCH];        // im2col(x2) hi  [p][k]
__device__ __half g_Al[LP * KPATCH];        // im2col(x2) lo
__device__ float  g_invn[LP];
__device__ float  g_mm[LP];
__device__ float  g_S[(size_t)LP * LP];     // fp32 scores  [p][q]
__device__ __half g_P[(size_t)LP * LP];     // softmax out (fp16)  [p][q]
__device__ __half g_rawh[(size_t)MRAW * LP]; // rawT fp16 [m][q]
__device__ float  g_cols[(size_t)MRAW * LP]; // GEMM2 out [m][pos]
__device__ float  g_y[(size_t)BATCH * C1N * H1N * W1N];

// ==================================================================
// mma.sync fp16 + ldmatrix + cp.async (base PTX, compiles at compute_103)
// ==================================================================
__device__ __forceinline__ void mma_f16(float d[4], const uint32_t a[4], const uint32_t b[2]) {
    asm volatile(
        "mma.sync.aligned.m16n8k16.row.col.f32.f16.f16.f32 "
        "{%0,%1,%2,%3},{%4,%5,%6,%7},{%8,%9},{%0,%1,%2,%3};"
        : "+f"(d[0]), "+f"(d[1]), "+f"(d[2]), "+f"(d[3])
        : "r"(a[0]), "r"(a[1]), "r"(a[2]), "r"(a[3]), "r"(b[0]), "r"(b[1]));
}
#define LDSM_X4(R, addr) \
    asm volatile("ldmatrix.sync.aligned.m8n8.x4.shared.b16 {%0,%1,%2,%3}, [%4];" \
        : "=r"((R)[0]), "=r"((R)[1]), "=r"((R)[2]), "=r"((R)[3]) : "r"(addr))

__device__ __forceinline__ uint32_t smem_u32(const void* p) {
    uint32_t a;
    asm("{ .reg .u64 t; cvta.to.shared.u64 t, %1; cvt.u32.u64 %0, t; }" : "=r"(a) : "l"(p));
    return a;
}
// L1-allocating async copy (tiles are re-read by many blocks)
__device__ __forceinline__ void cp16(uint32_t dst, const void* src) {
    asm volatile(
        "{ .reg .u64 gp; cvta.to.global.u64 gp, %1;"
        " cp.async.ca.shared.global [%0], [gp], 16; }"
        :: "r"(dst), "l"(src) : "memory");
}
#define CP_COMMIT() asm volatile("cp.async.commit_group;" ::: "memory")
#define CP_WAIT0()  asm volatile("cp.async.wait_group 0;" ::: "memory")

#define SSTR 20    // gemm1 smem row stride in u32 words (16 data + 4 pad)
#define SSTR2 36   // gemm2 smem row stride in u32 words (32 data + 4 pad)

// ==================================================================
// GEMM1 (symmetric): S[p][q] = <A_p, A_q> * invn[q].
// Lower-triangle blocks only; writes tile + transpose. fp16 2-term
// split, 3 MMA terms. K=576, BK=32, 8 warps, 128x128 tile, cp.async
// single-buffer, 2 CTAs/SM. 528 blocks.
// ==================================================================
__global__ void __launch_bounds__(256, 2) gemm1_mma() {
    __shared__ uint32_t sAh[128 * SSTR], sAl[128 * SSTR];
    __shared__ uint32_t sBh[128 * SSTR], sBl[128 * SSTR];
    const int K = KPATCH;
    int t = threadIdx.x;

    // triangular block decode: bx >= by
    int L = blockIdx.x;
    int bx = (int)((sqrtf(8.f * (float)L + 1.f) - 1.f) * 0.5f);
    while ((bx + 1) * (bx + 2) / 2 <= L) bx++;
    while (bx * (bx + 1) / 2 > L) bx--;
    int by = L - bx * (bx + 1) / 2;

    int m0 = by * 128, n0 = bx * 128;
    int wid = t >> 5, lane = t & 31;
    int wm = (wid >> 1) * 32, wn = (wid & 1) * 64;
    int g = lane >> 2, tig = lane & 3;

    float acc[2][8][4] = {};

    int lm = t >> 1;              // row 0..127
    int lw = (t & 1) * 8;         // u32-word offset within 16-word row
    const __half* pAh = g_Ah + (size_t)(m0 + lm) * K + lw * 2;
    const __half* pAl = g_Al + (size_t)(m0 + lm) * K + lw * 2;
    const __half* pBh = g_Ah + (size_t)(n0 + lm) * K + lw * 2;
    const __half* pBl = g_Al + (size_t)(n0 + lm) * K + lw * 2;
    uint32_t dAh = smem_u32(sAh) + (uint32_t)(lm * SSTR + lw) * 4;
    uint32_t dAl = smem_u32(sAl) + (uint32_t)(lm * SSTR + lw) * 4;
    uint32_t dBh = smem_u32(sBh) + (uint32_t)(lm * SSTR + lw) * 4;
    uint32_t dBl = smem_u32(sBl) + (uint32_t)(lm * SSTR + lw) * 4;

    // ldmatrix per-lane source rows/column-halves
    int rowA = lane & 15;
    int koffA = ((lane >> 4) & 1) * 4;
    int rowB = (lane & 7) + ((lane & 16) >> 1);
    int koffB = ((lane & 8) >> 1);
    uint32_t aWh = smem_u32(sAh) + 4 * ((wm + rowA) * SSTR + koffA);
    uint32_t aWl = smem_u32(sAl) + 4 * ((wm + rowA) * SSTR + koffA);
    uint32_t bWh = smem_u32(sBh) + 4 * ((wn + rowB) * SSTR + koffB);
    uint32_t bWl = smem_u32(sBl) + 4 * ((wn + rowB) * SSTR + koffB);

    const int NC = K / 32;
    for (int ci = 0; ci < NC; ci++) {
        int k0 = ci * 32;
        if (ci > 0) __syncthreads();
        cp16(dAh, pAh + k0);      cp16(dAh + 16, pAh + k0 + 8);
        cp16(dAl, pAl + k0);      cp16(dAl + 16, pAl + k0 + 8);
        cp16(dBh, pBh + k0);      cp16(dBh + 16, pBh + k0 + 8);
        cp16(dBl, pBl + k0);      cp16(dBl + 16, pBl + k0 + 8);
        CP_COMMIT();
        CP_WAIT0();
        __syncthreads();
#pragma unroll
        for (int s = 0; s < 2; s++) {
            uint32_t ah[2][4], al[2][4], bh[8][2], bl[8][2];
#pragma unroll
            for (int mt = 0; mt < 2; mt++) {
                uint32_t off = (uint32_t)(mt * 16 * SSTR + s * 8) * 4;
                LDSM_X4(ah[mt], aWh + off);
                LDSM_X4(al[mt], aWl + off);
            }
#pragma unroll
            for (int ntp = 0; ntp < 4; ntp++) {
                uint32_t off = (uint32_t)(ntp * 16 * SSTR + s * 8) * 4;
                LDSM_X4(&bh[2 * ntp][0], bWh + off);
                LDSM_X4(&bl[2 * ntp][0], bWl + off);
            }
#pragma unroll
            for (int mt = 0; mt < 2; mt++)
#pragma unroll
                for (int nt = 0; nt < 8; nt++) {
                    mma_f16(acc[mt][nt], ah[mt], bh[nt]);
                    mma_f16(acc[mt][nt], ah[mt], bl[nt]);
                    mma_f16(acc[mt][nt], al[mt], bh[nt]);
                }
        }
    }
    // epilogue: write tile (scale invn[col]) and transpose (scale invn[row])
#pragma unroll
    for (int mt = 0; mt < 2; mt++) {
        int row = m0 + wm + mt * 16 + g;
        float sr0 = __ldg(&g_invn[row]);
        float sr8 = __ldg(&g_invn[row + 8]);
#pragma unroll
        for (int nt = 0; nt < 8; nt++) {
            int col = n0 + wn + nt * 8 + 2 * tig;
            float s0 = __ldg(&g_invn[col]);
            float s1 = __ldg(&g_invn[col + 1]);
            *(float2*)(g_S + (size_t)row * LP + col) =
                make_float2(acc[mt][nt][0] * s0, acc[mt][nt][1] * s1);
            *(float2*)(g_S + (size_t)(row + 8) * LP + col) =
                make_float2(acc[mt][nt][2] * s0, acc[mt][nt][3] * s1);
            g_S[(size_t)col * LP + row]           = acc[mt][nt][0] * sr0;
            g_S[(size_t)(col + 1) * LP + row]     = acc[mt][nt][1] * sr0;
            g_S[(size_t)col * LP + row + 8]       = acc[mt][nt][2] * sr8;
            g_S[(size_t)(col + 1) * LP + row + 8] = acc[mt][nt][3] * sr8;
        }
    }
}

// ==================================================================
// GEMM2: cols[m][p] = sum_q raw[m][q] * P[p][q]
// A = raw fp16, B = P fp16 (1 MMA term). M=2048, N=4096, K=4096,
// BK=64, 8 warps, 128x128 tile, cp.async single-buffer, 2 CTAs/SM.
// ==================================================================
__global__ void __launch_bounds__(256, 2) gemm2_mma() {
    __shared__ uint32_t sA[128 * SSTR2];
    __shared__ uint32_t sB[128 * SSTR2];
    int t = threadIdx.x;
    int m0 = blockIdx.y * 128, n0 = blockIdx.x * 128;
    int wid = t >> 5, lane = t & 31;
    int wm = (wid >> 1) * 32, wn = (wid & 1) * 64;
    int g = lane >> 2, tig = lane & 3;

    float acc[2][8][4] = {};

    int lm = t >> 1;
    int lw = (t & 1) * 16;        // u32-word offset (half of 32-word row)
    const __half* pA = g_rawh + (size_t)(m0 + lm) * LP + lw * 2;
    const __half* pB = g_P    + (size_t)(n0 + lm) * LP + lw * 2;
    uint32_t dA = smem_u32(sA) + (uint32_t)(lm * SSTR2 + lw) * 4;
    uint32_t dB = smem_u32(sB) + (uint32_t)(lm * SSTR2 + lw) * 4;

    int rowA = lane & 15;
    int koffA = ((lane >> 4) & 1) * 4;
    int rowB = (lane & 7) + ((lane & 16) >> 1);
    int koffB = ((lane & 8) >> 1);
    uint32_t aW = smem_u32(sA) + 4 * ((wm + rowA) * SSTR2 + koffA);
    uint32_t bW = smem_u32(sB) + 4 * ((wn + rowB) * SSTR2 + koffB);

    const int NC = LP / 64;
    for (int ci = 0; ci < NC; ci++) {
        int k0 = ci * 64;
        if (ci > 0) __syncthreads();
#pragma unroll
        for (int j = 0; j < 4; j++) {
            cp16(dA + j * 16, pA + k0 + j * 8);
            cp16(dB + j * 16, pB + k0 + j * 8);
        }
        CP_COMMIT();
        CP_WAIT0();
        __syncthreads();
#pragma unroll
        for (int s = 0; s < 4; s++) {
            uint32_t a[2][4], b[8][2];
#pragma unroll
            for (int mt = 0; mt < 2; mt++) {
                uint32_t off = (uint32_t)(mt * 16 * SSTR2 + s * 8) * 4;
                LDSM_X4(a[mt], aW + off);
            }
#pragma unroll
            for (int ntp = 0; ntp < 4; ntp++) {
                uint32_t off = (uint32_t)(ntp * 16 * SSTR2 + s * 8) * 4;
                LDSM_X4(&b[2 * ntp][0], bW + off);
            }
#pragma unroll
            for (int mt = 0; mt < 2; mt++)
#pragma unroll
                for (int nt = 0; nt < 8; nt++)
                    mma_f16(acc[mt][nt], a[mt], b[nt]);
        }
    }
#pragma unroll
    for (int mt = 0; mt < 2; mt++) {
        int row = m0 + wm + mt * 16 + g;
#pragma unroll
        for (int nt = 0; nt < 8; nt++) {
            int col = n0 + wn + nt * 8 + 2 * tig;
            *(float2*)(g_cols + (size_t)row * LP + col) =
                make_float2(acc[mt][nt][0], acc[mt][nt][1]);
            *(float2*)(g_cols + (size_t)(row + 8) * LP + col) =
                make_float2(acc[mt][nt][2], acc[mt][nt][3]);
        }
    }
}

// ------------------------------------------------------------------
// im2col of x2 (k=3,s=1,pad=1) -> fp16 hi/lo split + inverse norms
// ------------------------------------------------------------------
__global__ void im2col_norm_kernel(const float* __restrict__ x2) {
    int p = blockIdx.x;
    int pi = p >> 6, pj = p & 63;
    int tid = threadIdx.x;
    float ss = 0.f;
    for (int k = tid; k < KPATCH; k += 256) {
        int c = k / 9, ki = k % 9;
        int ky = ki / 3, kx = ki % 3;
        int yy = pi - 1 + ky, xx = pj - 1 + kx;
        float v = 0.f;
        if (yy >= 0 && yy < H2N && xx >= 0 && xx < W2N)
            v = x2[(c * H2N + yy) * W2N + xx];
        __half h = __float2half_rn(v);
        g_Ah[p * KPATCH + k] = h;
        g_Al[p * KPATCH + k] = __float2half_rn(v - __half2float(h));
        ss += v * v;
    }
    __shared__ float red[256];
    red[tid] = ss;
    __syncthreads();
    for (int s = 128; s > 0; s >>= 1) {
        if (tid < s) red[tid] += red[tid + s];
        __syncthreads();
    }
    if (tid == 0) {
        float n = sqrtf(red[0]);
        g_invn[p] = 1.f / fmaxf(n, 1e-4f);
    }
}

// ------------------------------------------------------------------
// mask patches (k=4,s=2,pad=1): mm[q] = (sum == 0) ? 1 : 0
// ------------------------------------------------------------------
__global__ void mask_patch_kernel(const float* __restrict__ mask) {
    int q = blockIdx.x * blockDim.x + threadIdx.x;
    if (q >= LP) return;
    int qi = q >> 6, qj = q & 63;
    float s = 0.f;
    for (int ky = 0; ky < 4; ky++)
        for (int kx = 0; kx < 4; kx++) {
            int yy = 2 * qi - 1 + ky, xx = 2 * qj - 1 + kx;
            if (yy >= 0 && yy < H1N && xx >= 0 && xx < W1N)
                s += mask[yy * W1N + xx];
        }
    g_mm[q] = (s == 0.f) ? 1.f : 0.f;
}

// ------------------------------------------------------------------
// masked softmax over q for each row p; writes fp16 P
// ------------------------------------------------------------------
__global__ void __launch_bounds__(256) softmax_kernel(const float* __restrict__ mask_all) {
    int p = blockIdx.x;
    int tid = threadIdx.x;
    float map = mask_all[p];
    const float* row = g_S + (size_t)p * LP;
    __half* prow = g_P + (size_t)p * LP;

    float v[16];
    float lmax = -1e30f;
#pragma unroll
    for (int i = 0; i < 16; i++) {
        int q = tid + i * 256;
        float x = row[q] * g_mm[q] * map;
        v[i] = x;
        lmax = fmaxf(lmax, x);
    }
    __shared__ float red[256];
    red[tid] = lmax;
    __syncthreads();
    for (int s = 128; s > 0; s >>= 1) {
        if (tid < s) red[tid] = fmaxf(red[tid], red[tid + s]);
        __syncthreads();
    }
    float gmax = red[0];
    __syncthreads();

    float lsum = 0.f;
#pragma unroll
    for (int i = 0; i < 16; i++) {
        float e = expf(SCALE_F * (v[i] - gmax));
        v[i] = e;
        lsum += e;
    }
    red[tid] = lsum;
    __syncthreads();
    for (int s = 128; s > 0; s >>= 1) {
        if (tid < s) red[tid] += red[tid + s];
        __syncthreads();
    }
    float inv = 1.f / red[0];
#pragma unroll
    for (int i = 0; i < 16; i++) {
        int q = tid + i * 256;
        float pv = fmaxf(v[i] * inv * g_mm[q] * map, 1e-8f);
        prow[q] = __float2half_rn(pv);
    }
}

// ------------------------------------------------------------------
// rawT[m][q] -> fp16 (k=4, s=2, pad=1), m = o*16+ky*4+kx
// ------------------------------------------------------------------
__global__ void fill_raw_kernel(const float* __restrict__ x1) {
    int q = blockIdx.x * blockDim.x + threadIdx.x;
    int m = blockIdx.y;
    int o = m >> 4, kk = m & 15;
    int ky = kk >> 2, kx = kk & 3;
    int qi = q >> 6, qj = q & 63;
    int yy = 2 * qi - 1 + ky, xx = 2 * qj - 1 + kx;
    float v = 0.f;
    if (yy >= 0 && yy < H1N && xx >= 0 && xx < W1N)
        v = x1[(o * H1N + yy) * W1N + xx];
    g_rawh[(size_t)m * LP + q] = __float2half_rn(v);
}

// ------------------------------------------------------------------
// col2im gather: y[o,Y,X] = 0.25 * sum over <=4 entries of g_cols
// ------------------------------------------------------------------
__global__ void col2im_kernel(int b) {
    int idx = blockIdx.x * blockDim.x + threadIdx.x;
    int X = idx & 127;
    int Y = (idx >> 7) & 127;
    int o = idx >> 14;
    float acc = 0.f;
    int ky0 = (Y & 1) ? 0 : 1;
    int kx0 = (X & 1) ? 0 : 1;
#pragma unroll
    for (int t = 0; t < 2; t++) {
        int ky = ky0 + 2 * t;
        int i = (Y + 1 - ky) >> 1;
        if (i < 0 || i >= 64) continue;
#pragma unroll
        for (int u = 0; u < 2; u++) {
            int kx = kx0 + 2 * u;
            int j = (X + 1 - kx) >> 1;
            if (j < 0 || j >= 64) continue;
            acc += g_cols[(size_t)(o * 16 + ky * 4 + kx) * LP + i * 64 + j];
        }
    }
    g_y[(size_t)b * C1N * H1N * W1N + idx] = acc * 0.25f;
}

// ------------------------------------------------------------------
// final: 4 grouped dilated 3x3 convs (rates 1,2,4,8) + bias + relu
// ------------------------------------------------------------------
__global__ void __launch_bounds__(256) final_conv_kernel(
    const float* __restrict__ w, const float* __restrict__ bias, float* __restrict__ out)
{
    int tile = blockIdx.x;
    int g = blockIdx.y;
    int b = blockIdx.z;
    int r = 1 << g;  // rates 1,2,4,8
    int ty0 = (tile >> 3) * 16, tx0 = (tile & 7) * 16;
    int HW = 16 + 2 * r;
    __shared__ float yt[32 * 32];
    __shared__ float ws[144];
    int tid = threadIdx.x;
    int py = tid >> 4, px = tid & 15;

    float acc[16];
#pragma unroll
    for (int i = 0; i < 16; i++) acc[i] = 0.f;

    const float* yb = g_y + (size_t)b * C1N * H1N * W1N;
    for (int c = 0; c < C1N; c++) {
        for (int idx = tid; idx < HW * HW; idx += 256) {
            int iy = idx / HW, ix = idx % HW;
            int gy = ty0 - r + iy, gx = tx0 - r + ix;
            float v = 0.f;
            if (gy >= 0 && gy < H1N && gx >= 0 && gx < W1N)
                v = yb[(c * H1N + gy) * W1N + gx];
            yt[idx] = v;
        }
        if (tid < 144)
            ws[tid] = w[((g * 16 + tid / 9) * C1N + c) * 9 + tid % 9];
        __syncthreads();
#pragma unroll
        for (int ky = 0; ky < 3; ky++)
#pragma unroll
            for (int kx = 0; kx < 3; kx++) {
                float v = yt[(py + ky * r) * HW + px + kx * r];
#pragma unroll
                for (int oc = 0; oc < 16; oc++)
                    acc[oc] += v * ws[oc * 9 + ky * 3 + kx];
            }
        __syncthreads();
    }
    int Y = ty0 + py, X = tx0 + px;
#pragma unroll
    for (int oc = 0; oc < 16; oc++) {
        float o = acc[oc] + bias[g * 16 + oc];
        out[((size_t)(b * 64 + g * 16 + oc) * H1N + Y) * W1N + X] = fmaxf(o, 0.f);
    }
}

// ------------------------------------------------------------------
extern "C" void kernel_launch(void* const* d_in, const int* in_sizes, int n_in,
                              void* d_out, int out_size) {
    const float* x1       = (const float*)d_in[0];  // [4,128,128,128]
    const float* x2       = (const float*)d_in[1];  // [4,64,64,64]
    const float* mask     = (const float*)d_in[2];  // [4,1,128,128]
    const float* mask_all = (const float*)d_in[3];  // [4,1,64,64]
    const float* conv_w   = (const float*)d_in[4];  // [4,16,128,3,3]
    const float* conv_b   = (const float*)d_in[5];  // [4,16]
    float* out = (float*)d_out;

    static cudaStream_t s2 = nullptr;
    static cudaEvent_t evFork[BATCH], evJoin[BATCH];
    if (!s2) {
        cudaStreamCreateWithFlags(&s2, cudaStreamNonBlocking);
        for (int b = 0; b < BATCH; b++) {
            cudaEventCreateWithFlags(&evFork[b], cudaEventDisableTiming);
            cudaEventCreateWithFlags(&evJoin[b], cudaEventDisableTiming);
        }
    }

    for (int b = 0; b < BATCH; b++) {
        // fork: mask_patch + fill_raw run on s2, overlapped with im2col+gemm1
        cudaEventRecord(evFork[b], 0);
        cudaStreamWaitEvent(s2, evFork[b], 0);
        mask_patch_kernel<<<LP / 256, 256, 0, s2>>>(mask + (size_t)b * H1N * W1N);
        fill_raw_kernel<<<dim3(LP / 256, MRAW), 256, 0, s2>>>(x1 + (size_t)b * C1N * H1N * W1N);
        cudaEventRecord(evJoin[b], s2);

        im2col_norm_kernel<<<LP, 256>>>(x2 + (size_t)b * C2N * H2N * W2N);
        gemm1_mma<<<528, 256>>>();
        // join before softmax (needs g_mm); gemm2 (needs g_rawh) is later
        cudaStreamWaitEvent(0, evJoin[b], 0);
        softmax_kernel<<<LP, 256>>>(mask_all + (size_t)b * LP);
        gemm2_mma<<<dim3(32, 16), 256>>>();
        col2im_kernel<<<(C1N * H1N * W1N) / 256, 256>>>(b);
    }
    final_conv_kernel<<<dim3(64, 4, 4), 256>>>(conv_w, conv_b, out);
}

// round 13
// speedup vs baseline: 1.0982x; 1.0093x over previous
#include <cuda_runtime.h>
#include <cuda_fp16.h>
#include <math.h>
#include <stdint.h>

#define BATCH 4
#define C1N 128
#define H1N 128
#define W1N 128
#define C2N 64
#define H2N 64
#define W2N 64
#define LP 4096          // H2*W2 positions / patches
#define KPATCH 576       // C2 * 3 * 3
#define MRAW 2048        // C1 * 4 * 4
#define SCALE_F 10.0f

// ---- scratch (device globals: allocation-free) ----
__device__ __half g_Ah[LP * KPATCH];        // im2col(x2) hi  [p][k]
__device__ __half g_Al[LP * KPATCH];        // im2col(x2) lo
__device__ float  g_invn[LP];
__device__ float  g_mm[LP];
__device__ float  g_S[(size_t)LP * LP];     // fp32 scores  [p][q]
__device__ __half g_P[(size_t)LP * LP];     // softmax out (fp16)  [p][q]
__device__ __half g_rawh[(size_t)MRAW * LP]; // rawT fp16 [m][q]
__device__ float  g_cols[(size_t)MRAW * LP]; // GEMM2 out [m][pos]
__device__ float  g_y[(size_t)BATCH * C1N * H1N * W1N];

// ==================================================================
// mma.sync fp16 + ldmatrix + cp.async (base PTX, compiles at compute_103)
// ==================================================================
__device__ __forceinline__ void mma_f16(float d[4], const uint32_t a[4], const uint32_t b[2]) {
    asm volatile(
        "mma.sync.aligned.m16n8k16.row.col.f32.f16.f16.f32 "
        "{%0,%1,%2,%3},{%4,%5,%6,%7},{%8,%9},{%0,%1,%2,%3};"
        : "+f"(d[0]), "+f"(d[1]), "+f"(d[2]), "+f"(d[3])
        : "r"(a[0]), "r"(a[1]), "r"(a[2]), "r"(a[3]), "r"(b[0]), "r"(b[1]));
}
#define LDSM_X4(R, addr) \
    asm volatile("ldmatrix.sync.aligned.m8n8.x4.shared.b16 {%0,%1,%2,%3}, [%4];" \
        : "=r"((R)[0]), "=r"((R)[1]), "=r"((R)[2]), "=r"((R)[3]) : "r"(addr))

__device__ __forceinline__ uint32_t smem_u32(const void* p) {
    uint32_t a;
    asm("{ .reg .u64 t; cvta.to.shared.u64 t, %1; cvt.u32.u64 %0, t; }" : "=r"(a) : "l"(p));
    return a;
}
// L1-allocating async copy (tiles are re-read by many blocks)
__device__ __forceinline__ void cp16(uint32_t dst, const void* src) {
    asm volatile(
        "{ .reg .u64 gp; cvta.to.global.u64 gp, %1;"
        " cp.async.ca.shared.global [%0], [gp], 16; }"
        :: "r"(dst), "l"(src) : "memory");
}
#define CP_COMMIT() asm volatile("cp.async.commit_group;" ::: "memory")
#define CP_WAIT0()  asm volatile("cp.async.wait_group 0;" ::: "memory")

#define SSTR1 12   // gemm1 smem row stride in u32 words (8 data + 4 pad), BK=16
#define SSTR2 20   // gemm2 smem row stride in u32 words (16 data + 4 pad), BK=32
#define STG1 (128 * SSTR1)   // words per matrix per stage (gemm1)
#define STG2 (128 * SSTR2)   // words per matrix per stage (gemm2)

// ==================================================================
// GEMM1 (symmetric): S[p][q] = <A_p, A_q> * invn[q].
// Lower-triangle blocks only; writes tile + transpose. fp16 2-term
// split, 3 MMA terms. K=576, BK=16, 8 warps, 128x128 tile, cp.async
// 2-stage pipeline, 2 CTAs/SM (48 KB smem). 528 blocks.
// ==================================================================
__global__ void __launch_bounds__(256, 2) gemm1_mma() {
    // [Ah s0][Ah s1][Al s0][Al s1][Bh s0][Bh s1][Bl s0][Bl s1]
    __shared__ uint32_t sm[8 * STG1];
    const int K = KPATCH;
    int t = threadIdx.x;

    // triangular block decode: bx >= by
    int L = blockIdx.x;
    int bx = (int)((sqrtf(8.f * (float)L + 1.f) - 1.f) * 0.5f);
    while ((bx + 1) * (bx + 2) / 2 <= L) bx++;
    while (bx * (bx + 1) / 2 > L) bx--;
    int by = L - bx * (bx + 1) / 2;

    int m0 = by * 128, n0 = bx * 128;
    int wid = t >> 5, lane = t & 31;
    int wm = (wid >> 1) * 32, wn = (wid & 1) * 64;
    int g = lane >> 2, tig = lane & 3;

    float acc[2][8][4] = {};

    int lm = t >> 1;              // row 0..127
    int lw = (t & 1) * 4;         // u32-word offset within 8-word row
    const __half* pAh = g_Ah + (size_t)(m0 + lm) * K + lw * 2;
    const __half* pAl = g_Al + (size_t)(m0 + lm) * K + lw * 2;
    const __half* pBh = g_Ah + (size_t)(n0 + lm) * K + lw * 2;
    const __half* pBl = g_Al + (size_t)(n0 + lm) * K + lw * 2;

    uint32_t smb = smem_u32(sm);
    uint32_t stoff = (uint32_t)(lm * SSTR1 + lw) * 4;
    uint32_t dAh = smb + stoff;                       // + stage*STG1*4
    uint32_t dAl = smb + 2 * STG1 * 4 + stoff;
    uint32_t dBh = smb + 4 * STG1 * 4 + stoff;
    uint32_t dBl = smb + 6 * STG1 * 4 + stoff;
    const uint32_t SGB = STG1 * 4;   // stage bytes

    // ldmatrix per-lane source rows/column-halves
    int rowA = lane & 15;
    int koffA = ((lane >> 4) & 1) * 4;
    int rowB = (lane & 7) + ((lane & 16) >> 1);
    int koffB = ((lane & 8) >> 1);
    uint32_t aWh = smb + 4 * ((wm + rowA) * SSTR1 + koffA);
    uint32_t aWl = smb + 2 * STG1 * 4 + 4 * ((wm + rowA) * SSTR1 + koffA);
    uint32_t bWh = smb + 4 * STG1 * 4 + 4 * ((wn + rowB) * SSTR1 + koffB);
    uint32_t bWl = smb + 6 * STG1 * 4 + 4 * ((wn + rowB) * SSTR1 + koffB);

    const int NC = K / 16;
    // preload chunk 0 into stage 0
    cp16(dAh, pAh);  cp16(dAl, pAl);  cp16(dBh, pBh);  cp16(dBl, pBl);
    CP_COMMIT();

    for (int ci = 0; ci < NC; ci++) {
        CP_WAIT0();
        __syncthreads();
        uint32_t cur = (uint32_t)(ci & 1) * SGB;
        if (ci + 1 < NC) {
            uint32_t nxt = (uint32_t)((ci + 1) & 1) * SGB;
            int k0 = (ci + 1) * 16;
            cp16(dAh + nxt, pAh + k0);
            cp16(dAl + nxt, pAl + k0);
            cp16(dBh + nxt, pBh + k0);
            cp16(dBl + nxt, pBl + k0);
            CP_COMMIT();
        }
        uint32_t ah[2][4], al[2][4], bh[8][2], bl[8][2];
#pragma unroll
        for (int mt = 0; mt < 2; mt++) {
            uint32_t off = cur + (uint32_t)(mt * 16 * SSTR1) * 4;
            LDSM_X4(ah[mt], aWh + off);
            LDSM_X4(al[mt], aWl + off);
        }
#pragma unroll
        for (int ntp = 0; ntp < 4; ntp++) {
            uint32_t off = cur + (uint32_t)(ntp * 16 * SSTR1) * 4;
            LDSM_X4(&bh[2 * ntp][0], bWh + off);
            LDSM_X4(&bl[2 * ntp][0], bWl + off);
        }
#pragma unroll
        for (int mt = 0; mt < 2; mt++)
#pragma unroll
            for (int nt = 0; nt < 8; nt++) {
                mma_f16(acc[mt][nt], ah[mt], bh[nt]);
                mma_f16(acc[mt][nt], ah[mt], bl[nt]);
                mma_f16(acc[mt][nt], al[mt], bh[nt]);
            }
    }
    // epilogue: write tile (scale invn[col]) and transpose (scale invn[row])
#pragma unroll
    for (int mt = 0; mt < 2; mt++) {
        int row = m0 + wm + mt * 16 + g;
        float sr0 = __ldg(&g_invn[row]);
        float sr8 = __ldg(&g_invn[row + 8]);
#pragma unroll
        for (int nt = 0; nt < 8; nt++) {
            int col = n0 + wn + nt * 8 + 2 * tig;
            float s0 = __ldg(&g_invn[col]);
            float s1 = __ldg(&g_invn[col + 1]);
            *(float2*)(g_S + (size_t)row * LP + col) =
                make_float2(acc[mt][nt][0] * s0, acc[mt][nt][1] * s1);
            *(float2*)(g_S + (size_t)(row + 8) * LP + col) =
                make_float2(acc[mt][nt][2] * s0, acc[mt][nt][3] * s1);
            g_S[(size_t)col * LP + row]           = acc[mt][nt][0] * sr0;
            g_S[(size_t)(col + 1) * LP + row]     = acc[mt][nt][1] * sr0;
            g_S[(size_t)col * LP + row + 8]       = acc[mt][nt][2] * sr8;
            g_S[(size_t)(col + 1) * LP + row + 8] = acc[mt][nt][3] * sr8;
        }
    }
}

// ==================================================================
// GEMM2: cols[m][p] = sum_q raw[m][q] * P[p][q]
// A = raw fp16, B = P fp16 (1 MMA term). M=2048, N=4096, K=4096,
// BK=32, 8 warps, 128x128 tile, cp.async 2-stage, 2 CTAs/SM (40 KB).
// ==================================================================
__global__ void __launch_bounds__(256, 2) gemm2_mma() {
    // [A s0][A s1][B s0][B s1]
    __shared__ uint32_t sm[4 * STG2];
    int t = threadIdx.x;
    int m0 = blockIdx.y * 128, n0 = blockIdx.x * 128;
    int wid = t >> 5, lane = t & 31;
    int wm = (wid >> 1) * 32, wn = (wid & 1) * 64;
    int g = lane >> 2, tig = lane & 3;

    float acc[2][8][4] = {};

    int lm = t >> 1;
    int lw = (t & 1) * 8;         // u32-word offset within 16-word row
    const __half* pA = g_rawh + (size_t)(m0 + lm) * LP + lw * 2;
    const __half* pB = g_P    + (size_t)(n0 + lm) * LP + lw * 2;

    uint32_t smb = smem_u32(sm);
    uint32_t stoff = (uint32_t)(lm * SSTR2 + lw) * 4;
    uint32_t dA = smb + stoff;
    uint32_t dB = smb + 2 * STG2 * 4 + stoff;
    const uint32_t SGB = STG2 * 4;

    int rowA = lane & 15;
    int koffA = ((lane >> 4) & 1) * 4;
    int rowB = (lane & 7) + ((lane & 16) >> 1);
    int koffB = ((lane & 8) >> 1);
    uint32_t aW = smb + 4 * ((wm + rowA) * SSTR2 + koffA);
    uint32_t bW = smb + 2 * STG2 * 4 + 4 * ((wn + rowB) * SSTR2 + koffB);

    const int NC = LP / 32;
    // preload chunk 0 into stage 0
    cp16(dA, pA);        cp16(dA + 16, pA + 8);
    cp16(dB, pB);        cp16(dB + 16, pB + 8);
    CP_COMMIT();

    for (int ci = 0; ci < NC; ci++) {
        CP_WAIT0();
        __syncthreads();
        uint32_t cur = (uint32_t)(ci & 1) * SGB;
        if (ci + 1 < NC) {
            uint32_t nxt = (uint32_t)((ci + 1) & 1) * SGB;
            int k0 = (ci + 1) * 32;
            cp16(dA + nxt, pA + k0);       cp16(dA + nxt + 16, pA + k0 + 8);
            cp16(dB + nxt, pB + k0);       cp16(dB + nxt + 16, pB + k0 + 8);
            CP_COMMIT();
        }
#pragma unroll
        for (int s = 0; s < 2; s++) {
            uint32_t a[2][4], b[8][2];
#pragma unroll
            for (int mt = 0; mt < 2; mt++) {
                uint32_t off = cur + (uint32_t)(mt * 16 * SSTR2 + s * 8) * 4;
                LDSM_X4(a[mt], aW + off);
            }
#pragma unroll
            for (int ntp = 0; ntp < 4; ntp++) {
                uint32_t off = cur + (uint32_t)(ntp * 16 * SSTR2 + s * 8) * 4;
                LDSM_X4(&b[2 * ntp][0], bW + off);
            }
#pragma unroll
            for (int mt = 0; mt < 2; mt++)
#pragma unroll
                for (int nt = 0; nt < 8; nt++)
                    mma_f16(acc[mt][nt], a[mt], b[nt]);
        }
    }
#pragma unroll
    for (int mt = 0; mt < 2; mt++) {
        int row = m0 + wm + mt * 16 + g;
#pragma unroll
        for (int nt = 0; nt < 8; nt++) {
            int col = n0 + wn + nt * 8 + 2 * tig;
            *(float2*)(g_cols + (size_t)row * LP + col) =
                make_float2(acc[mt][nt][0], acc[mt][nt][1]);
            *(float2*)(g_cols + (size_t)(row + 8) * LP + col) =
                make_float2(acc[mt][nt][2], acc[mt][nt][3]);
        }
    }
}

// ------------------------------------------------------------------
// im2col of x2 (k=3,s=1,pad=1) -> fp16 hi/lo split + inverse norms
// ------------------------------------------------------------------
__global__ void im2col_norm_kernel(const float* __restrict__ x2) {
    int p = blockIdx.x;
    int pi = p >> 6, pj = p & 63;
    int tid = threadIdx.x;
    float ss = 0.f;
    for (int k = tid; k < KPATCH; k += 256) {
        int c = k / 9, ki = k % 9;
        int ky = ki / 3, kx = ki % 3;
        int yy = pi - 1 + ky, xx = pj - 1 + kx;
        float v = 0.f;
        if (yy >= 0 && yy < H2N && xx >= 0 && xx < W2N)
            v = x2[(c * H2N + yy) * W2N + xx];
        __half h = __float2half_rn(v);
        g_Ah[p * KPATCH + k] = h;
        g_Al[p * KPATCH + k] = __float2half_rn(v - __half2float(h));
        ss += v * v;
    }
    __shared__ float red[256];
    red[tid] = ss;
    __syncthreads();
    for (int s = 128; s > 0; s >>= 1) {
        if (tid < s) red[tid] += red[tid + s];
        __syncthreads();
    }
    if (tid == 0) {
        float n = sqrtf(red[0]);
        g_invn[p] = 1.f / fmaxf(n, 1e-4f);
    }
}

// ------------------------------------------------------------------
// mask patches (k=4,s=2,pad=1): mm[q] = (sum == 0) ? 1 : 0
// ------------------------------------------------------------------
__global__ void mask_patch_kernel(const float* __restrict__ mask) {
    int q = blockIdx.x * blockDim.x + threadIdx.x;
    if (q >= LP) return;
    int qi = q >> 6, qj = q & 63;
    float s = 0.f;
    for (int ky = 0; ky < 4; ky++)
        for (int kx = 0; kx < 4; kx++) {
            int yy = 2 * qi - 1 + ky, xx = 2 * qj - 1 + kx;
            if (yy >= 0 && yy < H1N && xx >= 0 && xx < W1N)
                s += mask[yy * W1N + xx];
        }
    g_mm[q] = (s == 0.f) ? 1.f : 0.f;
}

// ------------------------------------------------------------------
// masked softmax over q for each row p; writes fp16 P
// ------------------------------------------------------------------
__global__ void __launch_bounds__(256) softmax_kernel(const float* __restrict__ mask_all) {
    int p = blockIdx.x;
    int tid = threadIdx.x;
    float map = mask_all[p];
    const float* row = g_S + (size_t)p * LP;
    __half* prow = g_P + (size_t)p * LP;

    float v[16];
    float lmax = -1e30f;
#pragma unroll
    for (int i = 0; i < 16; i++) {
        int q = tid + i * 256;
        float x = row[q] * g_mm[q] * map;
        v[i] = x;
        lmax = fmaxf(lmax, x);
    }
    __shared__ float red[256];
    red[tid] = lmax;
    __syncthreads();
    for (int s = 128; s > 0; s >>= 1) {
        if (tid < s) red[tid] = fmaxf(red[tid], red[tid + s]);
        __syncthreads();
    }
    float gmax = red[0];
    __syncthreads();

    float lsum = 0.f;
#pragma unroll
    for (int i = 0; i < 16; i++) {
        float e = expf(SCALE_F * (v[i] - gmax));
        v[i] = e;
        lsum += e;
    }
    red[tid] = lsum;
    __syncthreads();
    for (int s = 128; s > 0; s >>= 1) {
        if (tid < s) red[tid] += red[tid + s];
        __syncthreads();
    }
    float inv = 1.f / red[0];
#pragma unroll
    for (int i = 0; i < 16; i++) {
        int q = tid + i * 256;
        float pv = fmaxf(v[i] * inv * g_mm[q] * map, 1e-8f);
        prow[q] = __float2half_rn(pv);
    }
}

// ------------------------------------------------------------------
// rawT[m][q] -> fp16 (k=4, s=2, pad=1), m = o*16+ky*4+kx
// ------------------------------------------------------------------
__global__ void fill_raw_kernel(const float* __restrict__ x1) {
    int q = blockIdx.x * blockDim.x + threadIdx.x;
    int m = blockIdx.y;
    int o = m >> 4, kk = m & 15;
    int ky = kk >> 2, kx = kk & 3;
    int qi = q >> 6, qj = q & 63;
    int yy = 2 * qi - 1 + ky, xx = 2 * qj - 1 + kx;
    float v = 0.f;
    if (yy >= 0 && yy < H1N && xx >= 0 && xx < W1N)
        v = x1[(o * H1N + yy) * W1N + xx];
    g_rawh[(size_t)m * LP + q] = __float2half_rn(v);
}

// ------------------------------------------------------------------
// col2im gather: y[o,Y,X] = 0.25 * sum over <=4 entries of g_cols
// ------------------------------------------------------------------
__global__ void col2im_kernel(int b) {
    int idx = blockIdx.x * blockDim.x + threadIdx.x;
    int X = idx & 127;
    int Y = (idx >> 7) & 127;
    int o = idx >> 14;
    float acc = 0.f;
    int ky0 = (Y & 1) ? 0 : 1;
    int kx0 = (X & 1) ? 0 : 1;
#pragma unroll
    for (int t = 0; t < 2; t++) {
        int ky = ky0 + 2 * t;
        int i = (Y + 1 - ky) >> 1;
        if (i < 0 || i >= 64) continue;
#pragma unroll
        for (int u = 0; u < 2; u++) {
            int kx = kx0 + 2 * u;
            int j = (X + 1 - kx) >> 1;
            if (j < 0 || j >= 64) continue;
            acc += g_cols[(size_t)(o * 16 + ky * 4 + kx) * LP + i * 64 + j];
        }
    }
    g_y[(size_t)b * C1N * H1N * W1N + idx] = acc * 0.25f;
}

// ------------------------------------------------------------------
// final: 4 grouped dilated 3x3 convs (rates 1,2,4,8) + bias + relu
// ------------------------------------------------------------------
__global__ void __launch_bounds__(256) final_conv_kernel(
    const float* __restrict__ w, const float* __restrict__ bias, float* __restrict__ out)
{
    int tile = blockIdx.x;
    int g = blockIdx.y;
    int b = blockIdx.z;
    int r = 1 << g;  // rates 1,2,4,8
    int ty0 = (tile >> 3) * 16, tx0 = (tile & 7) * 16;
    int HW = 16 + 2 * r;
    __shared__ float yt[32 * 32];
    __shared__ float ws[144];
    int tid = threadIdx.x;
    int py = tid >> 4, px = tid & 15;

    float acc[16];
#pragma unroll
    for (int i = 0; i < 16; i++) acc[i] = 0.f;

    const float* yb = g_y + (size_t)b * C1N * H1N * W1N;
    for (int c = 0; c < C1N; c++) {
        for (int idx = tid; idx < HW * HW; idx += 256) {
            int iy = idx / HW, ix = idx % HW;
            int gy = ty0 - r + iy, gx = tx0 - r + ix;
            float v = 0.f;
            if (gy >= 0 && gy < H1N && gx >= 0 && gx < W1N)
                v = yb[(c * H1N + gy) * W1N + gx];
            yt[idx] = v;
        }
        if (tid < 144)
            ws[tid] = w[((g * 16 + tid / 9) * C1N + c) * 9 + tid % 9];
        __syncthreads();
#pragma unroll
        for (int ky = 0; ky < 3; ky++)
#pragma unroll
            for (int kx = 0; kx < 3; kx++) {
                float v = yt[(py + ky * r) * HW + px + kx * r];
#pragma unroll
                for (int oc = 0; oc < 16; oc++)
                    acc[oc] += v * ws[oc * 9 + ky * 3 + kx];
            }
        __syncthreads();
    }
    int Y = ty0 + py, X = tx0 + px;
#pragma unroll
    for (int oc = 0; oc < 16; oc++) {
        float o = acc[oc] + bias[g * 16 + oc];
        out[((size_t)(b * 64 + g * 16 + oc) * H1N + Y) * W1N + X] = fmaxf(o, 0.f);
    }
}

// ------------------------------------------------------------------
extern "C" void kernel_launch(void* const* d_in, const int* in_sizes, int n_in,
                              void* d_out, int out_size) {
    const float* x1       = (const float*)d_in[0];  // [4,128,128,128]
    const float* x2       = (const float*)d_in[1];  // [4,64,64,64]
    const float* mask     = (const float*)d_in[2];  // [4,1,128,128]
    const float* mask_all = (const float*)d_in[3];  // [4,1,64,64]
    const float* conv_w   = (const float*)d_in[4];  // [4,16,128,3,3]
    const float* conv_b   = (const float*)d_in[5];  // [4,16]
    float* out = (float*)d_out;

    static cudaStream_t s2 = nullptr;
    static cudaEvent_t evFork[BATCH], evJoin[BATCH];
    if (!s2) {
        cudaStreamCreateWithFlags(&s2, cudaStreamNonBlocking);
        for (int b = 0; b < BATCH; b++) {
            cudaEventCreateWithFlags(&evFork[b], cudaEventDisableTiming);
            cudaEventCreateWithFlags(&evJoin[b], cudaEventDisableTiming);
        }
    }

    for (int b = 0; b < BATCH; b++) {
        // fork: mask_patch + fill_raw run on s2, overlapped with im2col+gemm1
        cudaEventRecord(evFork[b], 0);
        cudaStreamWaitEvent(s2, evFork[b], 0);
        mask_patch_kernel<<<LP / 256, 256, 0, s2>>>(mask + (size_t)b * H1N * W1N);
        fill_raw_kernel<<<dim3(LP / 256, MRAW), 256, 0, s2>>>(x1 + (size_t)b * C1N * H1N * W1N);
        cudaEventRecord(evJoin[b], s2);

        im2col_norm_kernel<<<LP, 256>>>(x2 + (size_t)b * C2N * H2N * W2N);
        gemm1_mma<<<528, 256>>>();
        // join before softmax (needs g_mm); gemm2 (needs g_rawh) is later
        cudaStreamWaitEvent(0, evJoin[b], 0);
        softmax_kernel<<<LP, 256>>>(mask_all + (size_t)b * LP);
        gemm2_mma<<<dim3(32, 16), 256>>>();
        col2im_kernel<<<(C1N * H1N * W1N) / 256, 256>>>(b);
    }
    final_conv_kernel<<<dim3(64, 4, 4), 256>>>(conv_w, conv_b, out);
}

// round 14
// speedup vs baseline: 1.2120x; 1.1036x over previous
#include <cuda_runtime.h>
#include <cuda_fp16.h>
#include <math.h>
#include <stdint.h>

#define BATCH 4
#define C1N 128
#define H1N 128
#define W1N 128
#define C2N 64
#define H2N 64
#define W2N 64
#define LP 4096          // H2*W2 positions / patches
#define KPATCH 576       // C2 * 3 * 3
#define MRAW 2048        // C1 * 4 * 4
#define SCALE_F 10.0f

// ---- scratch (device globals, double-buffered by batch parity) ----
__device__ __half g_Ah[2][LP * KPATCH];
__device__ __half g_Al[2][LP * KPATCH];
__device__ float  g_invn[2][LP];
__device__ float  g_mm[2][LP];
__device__ float  g_S[2][(size_t)LP * LP];
__device__ __half g_P[2][(size_t)LP * LP];
__device__ __half g_rawh[2][(size_t)MRAW * LP];
__device__ float  g_cols[2][(size_t)MRAW * LP];
__device__ float  g_y[(size_t)BATCH * C1N * H1N * W1N];

// ==================================================================
// mma.sync fp16 + ldmatrix + cp.async (base PTX, compiles at compute_103)
// ==================================================================
__device__ __forceinline__ void mma_f16(float d[4], const uint32_t a[4], const uint32_t b[2]) {
    asm volatile(
        "mma.sync.aligned.m16n8k16.row.col.f32.f16.f16.f32 "
        "{%0,%1,%2,%3},{%4,%5,%6,%7},{%8,%9},{%0,%1,%2,%3};"
        : "+f"(d[0]), "+f"(d[1]), "+f"(d[2]), "+f"(d[3])
        : "r"(a[0]), "r"(a[1]), "r"(a[2]), "r"(a[3]), "r"(b[0]), "r"(b[1]));
}
#define LDSM_X4(R, addr) \
    asm volatile("ldmatrix.sync.aligned.m8n8.x4.shared.b16 {%0,%1,%2,%3}, [%4];" \
        : "=r"((R)[0]), "=r"((R)[1]), "=r"((R)[2]), "=r"((R)[3]) : "r"(addr))

__device__ __forceinline__ uint32_t smem_u32(const void* p) {
    uint32_t a;
    asm("{ .reg .u64 t; cvta.to.shared.u64 t, %1; cvt.u32.u64 %0, t; }" : "=r"(a) : "l"(p));
    return a;
}
// L1-allocating async copy (tiles are re-read by many blocks)
__device__ __forceinline__ void cp16(uint32_t dst, const void* src) {
    asm volatile(
        "{ .reg .u64 gp; cvta.to.global.u64 gp, %1;"
        " cp.async.ca.shared.global [%0], [gp], 16; }"
        :: "r"(dst), "l"(src) : "memory");
}
#define CP_COMMIT() asm volatile("cp.async.commit_group;" ::: "memory")
#define CP_WAIT0()  asm volatile("cp.async.wait_group 0;" ::: "memory")

#define SSTR1 12   // gemm1 smem row stride in u32 words (8 data + 4 pad), BK=16
#define SSTR2 20   // gemm2 smem row stride in u32 words (16 data + 4 pad), BK=32
#define STG1 (128 * SSTR1)
#define STG2 (128 * SSTR2)

// ==================================================================
// GEMM1 (symmetric): S[p][q] = <A_p, A_q> * invn[q].
// Lower-triangle blocks only; writes tile + transpose. fp16 2-term
// split, 3 MMA terms. K=576, BK=16, 8 warps, 128x128 tile, cp.async
// 2-stage pipeline, 2 CTAs/SM. 528 blocks.
// ==================================================================
__global__ void __launch_bounds__(256, 2) gemm1_mma(int pb) {
    __shared__ uint32_t sm[8 * STG1];
    const int K = KPATCH;
    int t = threadIdx.x;

    int L = blockIdx.x;
    int bx = (int)((sqrtf(8.f * (float)L + 1.f) - 1.f) * 0.5f);
    while ((bx + 1) * (bx + 2) / 2 <= L) bx++;
    while (bx * (bx + 1) / 2 > L) bx--;
    int by = L - bx * (bx + 1) / 2;

    int m0 = by * 128, n0 = bx * 128;
    int wid = t >> 5, lane = t & 31;
    int wm = (wid >> 1) * 32, wn = (wid & 1) * 64;
    int g = lane >> 2, tig = lane & 3;

    const __half* Ah = g_Ah[pb];
    const __half* Al = g_Al[pb];
    const float* invn = g_invn[pb];
    float* S = g_S[pb];

    float acc[2][8][4] = {};

    int lm = t >> 1;
    int lw = (t & 1) * 4;
    const __half* pAh = Ah + (size_t)(m0 + lm) * K + lw * 2;
    const __half* pAl = Al + (size_t)(m0 + lm) * K + lw * 2;
    const __half* pBh = Ah + (size_t)(n0 + lm) * K + lw * 2;
    const __half* pBl = Al + (size_t)(n0 + lm) * K + lw * 2;

    uint32_t smb = smem_u32(sm);
    uint32_t stoff = (uint32_t)(lm * SSTR1 + lw) * 4;
    uint32_t dAh = smb + stoff;
    uint32_t dAl = smb + 2 * STG1 * 4 + stoff;
    uint32_t dBh = smb + 4 * STG1 * 4 + stoff;
    uint32_t dBl = smb + 6 * STG1 * 4 + stoff;
    const uint32_t SGB = STG1 * 4;

    int rowA = lane & 15;
    int koffA = ((lane >> 4) & 1) * 4;
    int rowB = (lane & 7) + ((lane & 16) >> 1);
    int koffB = ((lane & 8) >> 1);
    uint32_t aWh = smb + 4 * ((wm + rowA) * SSTR1 + koffA);
    uint32_t aWl = smb + 2 * STG1 * 4 + 4 * ((wm + rowA) * SSTR1 + koffA);
    uint32_t bWh = smb + 4 * STG1 * 4 + 4 * ((wn + rowB) * SSTR1 + koffB);
    uint32_t bWl = smb + 6 * STG1 * 4 + 4 * ((wn + rowB) * SSTR1 + koffB);

    const int NC = K / 16;
    cp16(dAh, pAh);  cp16(dAl, pAl);  cp16(dBh, pBh);  cp16(dBl, pBl);
    CP_COMMIT();

    for (int ci = 0; ci < NC; ci++) {
        CP_WAIT0();
        __syncthreads();
        uint32_t cur = (uint32_t)(ci & 1) * SGB;
        if (ci + 1 < NC) {
            uint32_t nxt = (uint32_t)((ci + 1) & 1) * SGB;
            int k0 = (ci + 1) * 16;
            cp16(dAh + nxt, pAh + k0);
            cp16(dAl + nxt, pAl + k0);
            cp16(dBh + nxt, pBh + k0);
            cp16(dBl + nxt, pBl + k0);
            CP_COMMIT();
        }
        uint32_t ah[2][4], al[2][4], bh[8][2], bl[8][2];
#pragma unroll
        for (int mt = 0; mt < 2; mt++) {
            uint32_t off = cur + (uint32_t)(mt * 16 * SSTR1) * 4;
            LDSM_X4(ah[mt], aWh + off);
            LDSM_X4(al[mt], aWl + off);
        }
#pragma unroll
        for (int ntp = 0; ntp < 4; ntp++) {
            uint32_t off = cur + (uint32_t)(ntp * 16 * SSTR1) * 4;
            LDSM_X4(&bh[2 * ntp][0], bWh + off);
            LDSM_X4(&bl[2 * ntp][0], bWl + off);
        }
#pragma unroll
        for (int mt = 0; mt < 2; mt++)
#pragma unroll
            for (int nt = 0; nt < 8; nt++) {
                mma_f16(acc[mt][nt], ah[mt], bh[nt]);
                mma_f16(acc[mt][nt], ah[mt], bl[nt]);
                mma_f16(acc[mt][nt], al[mt], bh[nt]);
            }
    }
#pragma unroll
    for (int mt = 0; mt < 2; mt++) {
        int row = m0 + wm + mt * 16 + g;
        float sr0 = __ldg(&invn[row]);
        float sr8 = __ldg(&invn[row + 8]);
#pragma unroll
        for (int nt = 0; nt < 8; nt++) {
            int col = n0 + wn + nt * 8 + 2 * tig;
            float s0 = __ldg(&invn[col]);
            float s1 = __ldg(&invn[col + 1]);
            *(float2*)(S + (size_t)row * LP + col) =
                make_float2(acc[mt][nt][0] * s0, acc[mt][nt][1] * s1);
            *(float2*)(S + (size_t)(row + 8) * LP + col) =
                make_float2(acc[mt][nt][2] * s0, acc[mt][nt][3] * s1);
            S[(size_t)col * LP + row]           = acc[mt][nt][0] * sr0;
            S[(size_t)(col + 1) * LP + row]     = acc[mt][nt][1] * sr0;
            S[(size_t)col * LP + row + 8]       = acc[mt][nt][2] * sr8;
            S[(size_t)(col + 1) * LP + row + 8] = acc[mt][nt][3] * sr8;
        }
    }
}

// ==================================================================
// GEMM2: cols[m][p] = sum_q raw[m][q] * P[p][q]
// A = raw fp16, B = P fp16. M=2048, N=4096, K=4096, BK=32,
// 8 warps, 128x128 tile, cp.async 2-stage, 2 CTAs/SM.
// ==================================================================
__global__ void __launch_bounds__(256, 2) gemm2_mma(int pb) {
    __shared__ uint32_t sm[4 * STG2];
    int t = threadIdx.x;
    int m0 = blockIdx.y * 128, n0 = blockIdx.x * 128;
    int wid = t >> 5, lane = t & 31;
    int wm = (wid >> 1) * 32, wn = (wid & 1) * 64;
    int g = lane >> 2, tig = lane & 3;

    float acc[2][8][4] = {};

    int lm = t >> 1;
    int lw = (t & 1) * 8;
    const __half* pA = g_rawh[pb] + (size_t)(m0 + lm) * LP + lw * 2;
    const __half* pB = g_P[pb]    + (size_t)(n0 + lm) * LP + lw * 2;
    float* cols = g_cols[pb];

    uint32_t smb = smem_u32(sm);
    uint32_t stoff = (uint32_t)(lm * SSTR2 + lw) * 4;
    uint32_t dA = smb + stoff;
    uint32_t dB = smb + 2 * STG2 * 4 + stoff;
    const uint32_t SGB = STG2 * 4;

    int rowA = lane & 15;
    int koffA = ((lane >> 4) & 1) * 4;
    int rowB = (lane & 7) + ((lane & 16) >> 1);
    int koffB = ((lane & 8) >> 1);
    uint32_t aW = smb + 4 * ((wm + rowA) * SSTR2 + koffA);
    uint32_t bW = smb + 2 * STG2 * 4 + 4 * ((wn + rowB) * SSTR2 + koffB);

    const int NC = LP / 32;
    cp16(dA, pA);        cp16(dA + 16, pA + 8);
    cp16(dB, pB);        cp16(dB + 16, pB + 8);
    CP_COMMIT();

    for (int ci = 0; ci < NC; ci++) {
        CP_WAIT0();
        __syncthreads();
        uint32_t cur = (uint32_t)(ci & 1) * SGB;
        if (ci + 1 < NC) {
            uint32_t nxt = (uint32_t)((ci + 1) & 1) * SGB;
            int k0 = (ci + 1) * 32;
            cp16(dA + nxt, pA + k0);       cp16(dA + nxt + 16, pA + k0 + 8);
            cp16(dB + nxt, pB + k0);       cp16(dB + nxt + 16, pB + k0 + 8);
            CP_COMMIT();
        }
#pragma unroll
        for (int s = 0; s < 2; s++) {
            uint32_t a[2][4], b[8][2];
#pragma unroll
            for (int mt = 0; mt < 2; mt++) {
                uint32_t off = cur + (uint32_t)(mt * 16 * SSTR2 + s * 8) * 4;
                LDSM_X4(a[mt], aW + off);
            }
#pragma unroll
            for (int ntp = 0; ntp < 4; ntp++) {
                uint32_t off = cur + (uint32_t)(ntp * 16 * SSTR2 + s * 8) * 4;
                LDSM_X4(&b[2 * ntp][0], bW + off);
            }
#pragma unroll
            for (int mt = 0; mt < 2; mt++)
#pragma unroll
                for (int nt = 0; nt < 8; nt++)
                    mma_f16(acc[mt][nt], a[mt], b[nt]);
        }
    }
#pragma unroll
    for (int mt = 0; mt < 2; mt++) {
        int row = m0 + wm + mt * 16 + g;
#pragma unroll
        for (int nt = 0; nt < 8; nt++) {
            int col = n0 + wn + nt * 8 + 2 * tig;
            *(float2*)(cols + (size_t)row * LP + col) =
                make_float2(acc[mt][nt][0], acc[mt][nt][1]);
            *(float2*)(cols + (size_t)(row + 8) * LP + col) =
                make_float2(acc[mt][nt][2], acc[mt][nt][3]);
        }
    }
}

// ------------------------------------------------------------------
// im2col of x2 (k=3,s=1,pad=1) -> fp16 hi/lo split + inverse norms
// ------------------------------------------------------------------
__global__ void im2col_norm_kernel(const float* __restrict__ x2, int pb) {
    int p = blockIdx.x;
    int pi = p >> 6, pj = p & 63;
    int tid = threadIdx.x;
    float ss = 0.f;
    for (int k = tid; k < KPATCH; k += 256) {
        int c = k / 9, ki = k % 9;
        int ky = ki / 3, kx = ki % 3;
        int yy = pi - 1 + ky, xx = pj - 1 + kx;
        float v = 0.f;
        if (yy >= 0 && yy < H2N && xx >= 0 && xx < W2N)
            v = x2[(c * H2N + yy) * W2N + xx];
        __half h = __float2half_rn(v);
        g_Ah[pb][p * KPATCH + k] = h;
        g_Al[pb][p * KPATCH + k] = __float2half_rn(v - __half2float(h));
        ss += v * v;
    }
    __shared__ float red[256];
    red[tid] = ss;
    __syncthreads();
    for (int s = 128; s > 0; s >>= 1) {
        if (tid < s) red[tid] += red[tid + s];
        __syncthreads();
    }
    if (tid == 0) {
        float n = sqrtf(red[0]);
        g_invn[pb][p] = 1.f / fmaxf(n, 1e-4f);
    }
}

// ------------------------------------------------------------------
// mask patches (k=4,s=2,pad=1): mm[q] = (sum == 0) ? 1 : 0
// ------------------------------------------------------------------
__global__ void mask_patch_kernel(const float* __restrict__ mask, int pb) {
    int q = blockIdx.x * blockDim.x + threadIdx.x;
    if (q >= LP) return;
    int qi = q >> 6, qj = q & 63;
    float s = 0.f;
    for (int ky = 0; ky < 4; ky++)
        for (int kx = 0; kx < 4; kx++) {
            int yy = 2 * qi - 1 + ky, xx = 2 * qj - 1 + kx;
            if (yy >= 0 && yy < H1N && xx >= 0 && xx < W1N)
                s += mask[yy * W1N + xx];
        }
    g_mm[pb][q] = (s == 0.f) ? 1.f : 0.f;
}

// ------------------------------------------------------------------
// masked softmax over q for each row p; writes fp16 P
// ------------------------------------------------------------------
__global__ void __launch_bounds__(256) softmax_kernel(const float* __restrict__ mask_all, int pb) {
    int p = blockIdx.x;
    int tid = threadIdx.x;
    float map = mask_all[p];
    const float* row = g_S[pb] + (size_t)p * LP;
    const float* mm = g_mm[pb];
    __half* prow = g_P[pb] + (size_t)p * LP;

    float v[16];
    float lmax = -1e30f;
#pragma unroll
    for (int i = 0; i < 16; i++) {
        int q = tid + i * 256;
        float x = row[q] * mm[q] * map;
        v[i] = x;
        lmax = fmaxf(lmax, x);
    }
    __shared__ float red[256];
    red[tid] = lmax;
    __syncthreads();
    for (int s = 128; s > 0; s >>= 1) {
        if (tid < s) red[tid] = fmaxf(red[tid], red[tid + s]);
        __syncthreads();
    }
    float gmax = red[0];
    __syncthreads();

    float lsum = 0.f;
#pragma unroll
    for (int i = 0; i < 16; i++) {
        float e = expf(SCALE_F * (v[i] - gmax));
        v[i] = e;
        lsum += e;
    }
    red[tid] = lsum;
    __syncthreads();
    for (int s = 128; s > 0; s >>= 1) {
        if (tid < s) red[tid] += red[tid + s];
        __syncthreads();
    }
    float inv = 1.f / red[0];
#pragma unroll
    for (int i = 0; i < 16; i++) {
        int q = tid + i * 256;
        float pv = fmaxf(v[i] * inv * mm[q] * map, 1e-8f);
        prow[q] = __float2half_rn(pv);
    }
}

// ------------------------------------------------------------------
// rawT[m][q] -> fp16 (k=4, s=2, pad=1), m = o*16+ky*4+kx
// ------------------------------------------------------------------
__global__ void fill_raw_kernel(const float* __restrict__ x1, int pb) {
    int q = blockIdx.x * blockDim.x + threadIdx.x;
    int m = blockIdx.y;
    int o = m >> 4, kk = m & 15;
    int ky = kk >> 2, kx = kk & 3;
    int qi = q >> 6, qj = q & 63;
    int yy = 2 * qi - 1 + ky, xx = 2 * qj - 1 + kx;
    float v = 0.f;
    if (yy >= 0 && yy < H1N && xx >= 0 && xx < W1N)
        v = x1[(o * H1N + yy) * W1N + xx];
    g_rawh[pb][(size_t)m * LP + q] = __float2half_rn(v);
}

// ------------------------------------------------------------------
// col2im gather: y[o,Y,X] = 0.25 * sum over <=4 entries of cols
// ------------------------------------------------------------------
__global__ void col2im_kernel(int b, int pb) {
    int idx = blockIdx.x * blockDim.x + threadIdx.x;
    int X = idx & 127;
    int Y = (idx >> 7) & 127;
    int o = idx >> 14;
    const float* cols = g_cols[pb];
    float acc = 0.f;
    int ky0 = (Y & 1) ? 0 : 1;
    int kx0 = (X & 1) ? 0 : 1;
#pragma unroll
    for (int t = 0; t < 2; t++) {
        int ky = ky0 + 2 * t;
        int i = (Y + 1 - ky) >> 1;
        if (i < 0 || i >= 64) continue;
#pragma unroll
        for (int u = 0; u < 2; u++) {
            int kx = kx0 + 2 * u;
            int j = (X + 1 - kx) >> 1;
            if (j < 0 || j >= 64) continue;
            acc += cols[(size_t)(o * 16 + ky * 4 + kx) * LP + i * 64 + j];
        }
    }
    g_y[(size_t)b * C1N * H1N * W1N + idx] = acc * 0.25f;
}

// ------------------------------------------------------------------
// final: 4 grouped dilated 3x3 convs (rates 1,2,4,8) + bias + relu
// ------------------------------------------------------------------
__global__ void __launch_bounds__(256) final_conv_kernel(
    const float* __restrict__ w, const float* __restrict__ bias, float* __restrict__ out)
{
    int tile = blockIdx.x;
    int g = blockIdx.y;
    int b = blockIdx.z;
    int r = 1 << g;  // rates 1,2,4,8
    int ty0 = (tile >> 3) * 16, tx0 = (tile & 7) * 16;
    int HW = 16 + 2 * r;
    __shared__ float yt[32 * 32];
    __shared__ float ws[144];
    int tid = threadIdx.x;
    int py = tid >> 4, px = tid & 15;

    float acc[16];
#pragma unroll
    for (int i = 0; i < 16; i++) acc[i] = 0.f;

    const float* yb = g_y + (size_t)b * C1N * H1N * W1N;
    for (int c = 0; c < C1N; c++) {
        for (int idx = tid; idx < HW * HW; idx += 256) {
            int iy = idx / HW, ix = idx % HW;
            int gy = ty0 - r + iy, gx = tx0 - r + ix;
            float v = 0.f;
            if (gy >= 0 && gy < H1N && gx >= 0 && gx < W1N)
                v = yb[(c * H1N + gy) * W1N + gx];
            yt[idx] = v;
        }
        if (tid < 144)
            ws[tid] = w[((g * 16 + tid / 9) * C1N + c) * 9 + tid % 9];
        __syncthreads();
#pragma unroll
        for (int ky = 0; ky < 3; ky++)
#pragma unroll
            for (int kx = 0; kx < 3; kx++) {
                float v = yt[(py + ky * r) * HW + px + kx * r];
#pragma unroll
                for (int oc = 0; oc < 16; oc++)
                    acc[oc] += v * ws[oc * 9 + ky * 3 + kx];
            }
        __syncthreads();
    }
    int Y = ty0 + py, X = tx0 + px;
#pragma unroll
    for (int oc = 0; oc < 16; oc++) {
        float o = acc[oc] + bias[g * 16 + oc];
        out[((size_t)(b * 64 + g * 16 + oc) * H1N + Y) * W1N + X] = fmaxf(o, 0.f);
    }
}

// ------------------------------------------------------------------
extern "C" void kernel_launch(void* const* d_in, const int* in_sizes, int n_in,
                              void* d_out, int out_size) {
    const float* x1       = (const float*)d_in[0];  // [4,128,128,128]
    const float* x2       = (const float*)d_in[1];  // [4,64,64,64]
    const float* mask     = (const float*)d_in[2];  // [4,1,128,128]
    const float* mask_all = (const float*)d_in[3];  // [4,1,64,64]
    const float* conv_w   = (const float*)d_in[4];  // [4,16,128,3,3]
    const float* conv_b   = (const float*)d_in[5];  // [4,16]
    float* out = (float*)d_out;

    static cudaStream_t s2 = nullptr;
    static cudaEvent_t evFork, evJoin;
    if (!s2) {
        cudaStreamCreateWithFlags(&s2, cudaStreamNonBlocking);
        cudaEventCreateWithFlags(&evFork, cudaEventDisableTiming);
        cudaEventCreateWithFlags(&evJoin, cudaEventDisableTiming);
    }

    // fork s2 into the capture
    cudaEventRecord(evFork, 0);
    cudaStreamWaitEvent(s2, evFork, 0);

    for (int b = 0; b < BATCH; b++) {
        cudaStream_t st = (b & 1) ? s2 : 0;
        int pb = b & 1;
        mask_patch_kernel<<<LP / 256, 256, 0, st>>>(mask + (size_t)b * H1N * W1N, pb);
        im2col_norm_kernel<<<LP, 256, 0, st>>>(x2 + (size_t)b * C2N * H2N * W2N, pb);
        fill_raw_kernel<<<dim3(LP / 256, MRAW), 256, 0, st>>>(x1 + (size_t)b * C1N * H1N * W1N, pb);
        gemm1_mma<<<528, 256, 0, st>>>(pb);
        softmax_kernel<<<LP, 256, 0, st>>>(mask_all + (size_t)b * LP, pb);
        gemm2_mma<<<dim3(32, 16), 256, 0, st>>>(pb);
        col2im_kernel<<<(C1N * H1N * W1N) / 256, 256, 0, st>>>(b, pb);
    }

    // join odd-batch chain back into stream 0 before final conv
    cudaEventRecord(evJoin, s2);
    cudaStreamWaitEvent(0, evJoin, 0);
    final_conv_kernel<<<dim3(64, 4, 4), 256>>>(conv_w, conv_b, out);
}

// round 15
// speedup vs baseline: 1.2617x; 1.0411x over previous
#include <cuda_runtime.h>
#include <cuda_fp16.h>
#include <math.h>
#include <stdint.h>

#define BATCH 4
#define C1N 128
#define H1N 128
#define W1N 128
#define C2N 64
#define H2N 64
#define W2N 64
#define LP 4096          // H2*W2 positions / patches
#define KPATCH 576       // C2 * 3 * 3
#define MRAW 2048        // C1 * 4 * 4
#define SCALE_F 10.0f

// ---- scratch (device globals, one set per batch for 4-way overlap) ----
__device__ __half g_Ah[BATCH][LP * KPATCH];
__device__ __half g_Al[BATCH][LP * KPATCH];
__device__ float  g_invn[BATCH][LP];
__device__ float  g_mm[BATCH][LP];
__device__ float  g_S[BATCH][(size_t)LP * LP];
__device__ __half g_P[BATCH][(size_t)LP * LP];
__device__ __half g_rawh[BATCH][(size_t)MRAW * LP];
__device__ float  g_cols[BATCH][(size_t)MRAW * LP];
__device__ float  g_y[(size_t)BATCH * C1N * H1N * W1N];

// ==================================================================
// mma.sync fp16 + ldmatrix + cp.async (base PTX, compiles at compute_103)
// ==================================================================
__device__ __forceinline__ void mma_f16(float d[4], const uint32_t a[4], const uint32_t b[2]) {
    asm volatile(
        "mma.sync.aligned.m16n8k16.row.col.f32.f16.f16.f32 "
        "{%0,%1,%2,%3},{%4,%5,%6,%7},{%8,%9},{%0,%1,%2,%3};"
        : "+f"(d[0]), "+f"(d[1]), "+f"(d[2]), "+f"(d[3])
        : "r"(a[0]), "r"(a[1]), "r"(a[2]), "r"(a[3]), "r"(b[0]), "r"(b[1]));
}
#define LDSM_X4(R, addr) \
    asm volatile("ldmatrix.sync.aligned.m8n8.x4.shared.b16 {%0,%1,%2,%3}, [%4];" \
        : "=r"((R)[0]), "=r"((R)[1]), "=r"((R)[2]), "=r"((R)[3]) : "r"(addr))

__device__ __forceinline__ uint32_t smem_u32(const void* p) {
    uint32_t a;
    asm("{ .reg .u64 t; cvta.to.shared.u64 t, %1; cvt.u32.u64 %0, t; }" : "=r"(a) : "l"(p));
    return a;
}
// L1-allocating async copy (tiles are re-read by many blocks)
__device__ __forceinline__ void cp16(uint32_t dst, const void* src) {
    asm volatile(
        "{ .reg .u64 gp; cvta.to.global.u64 gp, %1;"
        " cp.async.ca.shared.global [%0], [gp], 16; }"
        :: "r"(dst), "l"(src) : "memory");
}
#define CP_COMMIT() asm volatile("cp.async.commit_group;" ::: "memory")
#define CP_WAIT0()  asm volatile("cp.async.wait_group 0;" ::: "memory")

#define SSTR1 12   // gemm1 smem row stride in u32 words (8 data + 4 pad), BK=16
#define SSTR2 20   // gemm2 smem row stride in u32 words (16 data + 4 pad), BK=32
#define STG1 (128 * SSTR1)
#define STG2 (128 * SSTR2)

// ==================================================================
// GEMM1 (symmetric): S[p][q] = <A_p, A_q> * invn[q].
// Lower-triangle blocks only; writes tile + transpose. fp16 2-term
// split, 3 MMA terms. K=576, BK=16, 8 warps, 128x128 tile, cp.async
// 2-stage pipeline, 2 CTAs/SM. 528 blocks.
// ==================================================================
__global__ void __launch_bounds__(256, 2) gemm1_mma(int pb) {
    __shared__ uint32_t sm[8 * STG1];
    const int K = KPATCH;
    int t = threadIdx.x;

    int L = blockIdx.x;
    int bx = (int)((sqrtf(8.f * (float)L + 1.f) - 1.f) * 0.5f);
    while ((bx + 1) * (bx + 2) / 2 <= L) bx++;
    while (bx * (bx + 1) / 2 > L) bx--;
    int by = L - bx * (bx + 1) / 2;

    int m0 = by * 128, n0 = bx * 128;
    int wid = t >> 5, lane = t & 31;
    int wm = (wid >> 1) * 32, wn = (wid & 1) * 64;
    int g = lane >> 2, tig = lane & 3;

    const __half* Ah = g_Ah[pb];
    const __half* Al = g_Al[pb];
    const float* invn = g_invn[pb];
    float* S = g_S[pb];

    float acc[2][8][4] = {};

    int lm = t >> 1;
    int lw = (t & 1) * 4;
    const __half* pAh = Ah + (size_t)(m0 + lm) * K + lw * 2;
    const __half* pAl = Al + (size_t)(m0 + lm) * K + lw * 2;
    const __half* pBh = Ah + (size_t)(n0 + lm) * K + lw * 2;
    const __half* pBl = Al + (size_t)(n0 + lm) * K + lw * 2;

    uint32_t smb = smem_u32(sm);
    uint32_t stoff = (uint32_t)(lm * SSTR1 + lw) * 4;
    uint32_t dAh = smb + stoff;
    uint32_t dAl = smb + 2 * STG1 * 4 + stoff;
    uint32_t dBh = smb + 4 * STG1 * 4 + stoff;
    uint32_t dBl = smb + 6 * STG1 * 4 + stoff;
    const uint32_t SGB = STG1 * 4;

    int rowA = lane & 15;
    int koffA = ((lane >> 4) & 1) * 4;
    int rowB = (lane & 7) + ((lane & 16) >> 1);
    int koffB = ((lane & 8) >> 1);
    uint32_t aWh = smb + 4 * ((wm + rowA) * SSTR1 + koffA);
    uint32_t aWl = smb + 2 * STG1 * 4 + 4 * ((wm + rowA) * SSTR1 + koffA);
    uint32_t bWh = smb + 4 * STG1 * 4 + 4 * ((wn + rowB) * SSTR1 + koffB);
    uint32_t bWl = smb + 6 * STG1 * 4 + 4 * ((wn + rowB) * SSTR1 + koffB);

    const int NC = K / 16;
    cp16(dAh, pAh);  cp16(dAl, pAl);  cp16(dBh, pBh);  cp16(dBl, pBl);
    CP_COMMIT();

    for (int ci = 0; ci < NC; ci++) {
        CP_WAIT0();
        __syncthreads();
        uint32_t cur = (uint32_t)(ci & 1) * SGB;
        if (ci + 1 < NC) {
            uint32_t nxt = (uint32_t)((ci + 1) & 1) * SGB;
            int k0 = (ci + 1) * 16;
            cp16(dAh + nxt, pAh + k0);
            cp16(dAl + nxt, pAl + k0);
            cp16(dBh + nxt, pBh + k0);
            cp16(dBl + nxt, pBl + k0);
            CP_COMMIT();
        }
        uint32_t ah[2][4], al[2][4], bh[8][2], bl[8][2];
#pragma unroll
        for (int mt = 0; mt < 2; mt++) {
            uint32_t off = cur + (uint32_t)(mt * 16 * SSTR1) * 4;
            LDSM_X4(ah[mt], aWh + off);
            LDSM_X4(al[mt], aWl + off);
        }
#pragma unroll
        for (int ntp = 0; ntp < 4; ntp++) {
            uint32_t off = cur + (uint32_t)(ntp * 16 * SSTR1) * 4;
            LDSM_X4(&bh[2 * ntp][0], bWh + off);
            LDSM_X4(&bl[2 * ntp][0], bWl + off);
        }
#pragma unroll
        for (int mt = 0; mt < 2; mt++)
#pragma unroll
            for (int nt = 0; nt < 8; nt++) {
                mma_f16(acc[mt][nt], ah[mt], bh[nt]);
                mma_f16(acc[mt][nt], ah[mt], bl[nt]);
                mma_f16(acc[mt][nt], al[mt], bh[nt]);
            }
    }
#pragma unroll
    for (int mt = 0; mt < 2; mt++) {
        int row = m0 + wm + mt * 16 + g;
        float sr0 = __ldg(&invn[row]);
        float sr8 = __ldg(&invn[row + 8]);
#pragma unroll
        for (int nt = 0; nt < 8; nt++) {
            int col = n0 + wn + nt * 8 + 2 * tig;
            float s0 = __ldg(&invn[col]);
            float s1 = __ldg(&invn[col + 1]);
            *(float2*)(S + (size_t)row * LP + col) =
                make_float2(acc[mt][nt][0] * s0, acc[mt][nt][1] * s1);
            *(float2*)(S + (size_t)(row + 8) * LP + col) =
                make_float2(acc[mt][nt][2] * s0, acc[mt][nt][3] * s1);
            S[(size_t)col * LP + row]           = acc[mt][nt][0] * sr0;
            S[(size_t)(col + 1) * LP + row]     = acc[mt][nt][1] * sr0;
            S[(size_t)col * LP + row + 8]       = acc[mt][nt][2] * sr8;
            S[(size_t)(col + 1) * LP + row + 8] = acc[mt][nt][3] * sr8;
        }
    }
}

// ==================================================================
// GEMM2: cols[m][p] = sum_q raw[m][q] * P[p][q]
// A = raw fp16, B = P fp16. M=2048, N=4096, K=4096, BK=32,
// 8 warps, 128x128 tile, cp.async 2-stage, 2 CTAs/SM.
// ==================================================================
__global__ void __launch_bounds__(256, 2) gemm2_mma(int pb) {
    __shared__ uint32_t sm[4 * STG2];
    int t = threadIdx.x;
    int m0 = blockIdx.y * 128, n0 = blockIdx.x * 128;
    int wid = t >> 5, lane = t & 31;
    int wm = (wid >> 1) * 32, wn = (wid & 1) * 64;
    int g = lane >> 2, tig = lane & 3;

    float acc[2][8][4] = {};

    int lm = t >> 1;
    int lw = (t & 1) * 8;
    const __half* pA = g_rawh[pb] + (size_t)(m0 + lm) * LP + lw * 2;
    const __half* pB = g_P[pb]    + (size_t)(n0 + lm) * LP + lw * 2;
    float* cols = g_cols[pb];

    uint32_t smb = smem_u32(sm);
    uint32_t stoff = (uint32_t)(lm * SSTR2 + lw) * 4;
    uint32_t dA = smb + stoff;
    uint32_t dB = smb + 2 * STG2 * 4 + stoff;
    const uint32_t SGB = STG2 * 4;

    int rowA = lane & 15;
    int koffA = ((lane >> 4) & 1) * 4;
    int rowB = (lane & 7) + ((lane & 16) >> 1);
    int koffB = ((lane & 8) >> 1);
    uint32_t aW = smb + 4 * ((wm + rowA) * SSTR2 + koffA);
    uint32_t bW = smb + 2 * STG2 * 4 + 4 * ((wn + rowB) * SSTR2 + koffB);

    const int NC = LP / 32;
    cp16(dA, pA);        cp16(dA + 16, pA + 8);
    cp16(dB, pB);        cp16(dB + 16, pB + 8);
    CP_COMMIT();

    for (int ci = 0; ci < NC; ci++) {
        CP_WAIT0();
        __syncthreads();
        uint32_t cur = (uint32_t)(ci & 1) * SGB;
        if (ci + 1 < NC) {
            uint32_t nxt = (uint32_t)((ci + 1) & 1) * SGB;
            int k0 = (ci + 1) * 32;
            cp16(dA + nxt, pA + k0);       cp16(dA + nxt + 16, pA + k0 + 8);
            cp16(dB + nxt, pB + k0);       cp16(dB + nxt + 16, pB + k0 + 8);
            CP_COMMIT();
        }
#pragma unroll
        for (int s = 0; s < 2; s++) {
            uint32_t a[2][4], b[8][2];
#pragma unroll
            for (int mt = 0; mt < 2; mt++) {
                uint32_t off = cur + (uint32_t)(mt * 16 * SSTR2 + s * 8) * 4;
                LDSM_X4(a[mt], aW + off);
            }
#pragma unroll
            for (int ntp = 0; ntp < 4; ntp++) {
                uint32_t off = cur + (uint32_t)(ntp * 16 * SSTR2 + s * 8) * 4;
                LDSM_X4(&b[2 * ntp][0], bW + off);
            }
#pragma unroll
            for (int mt = 0; mt < 2; mt++)
#pragma unroll
                for (int nt = 0; nt < 8; nt++)
                    mma_f16(acc[mt][nt], a[mt], b[nt]);
        }
    }
#pragma unroll
    for (int mt = 0; mt < 2; mt++) {
        int row = m0 + wm + mt * 16 + g;
#pragma unroll
        for (int nt = 0; nt < 8; nt++) {
            int col = n0 + wn + nt * 8 + 2 * tig;
            *(float2*)(cols + (size_t)row * LP + col) =
                make_float2(acc[mt][nt][0], acc[mt][nt][1]);
            *(float2*)(cols + (size_t)(row + 8) * LP + col) =
                make_float2(acc[mt][nt][2], acc[mt][nt][3]);
        }
    }
}

// ------------------------------------------------------------------
// im2col of x2 (k=3,s=1,pad=1) -> fp16 hi/lo split + inverse norms
// ------------------------------------------------------------------
__global__ void im2col_norm_kernel(const float* __restrict__ x2, int pb) {
    int p = blockIdx.x;
    int pi = p >> 6, pj = p & 63;
    int tid = threadIdx.x;
    float ss = 0.f;
    for (int k = tid; k < KPATCH; k += 256) {
        int c = k / 9, ki = k % 9;
        int ky = ki / 3, kx = ki % 3;
        int yy = pi - 1 + ky, xx = pj - 1 + kx;
        float v = 0.f;
        if (yy >= 0 && yy < H2N && xx >= 0 && xx < W2N)
            v = x2[(c * H2N + yy) * W2N + xx];
        __half h = __float2half_rn(v);
        g_Ah[pb][p * KPATCH + k] = h;
        g_Al[pb][p * KPATCH + k] = __float2half_rn(v - __half2float(h));
        ss += v * v;
    }
    __shared__ float red[256];
    red[tid] = ss;
    __syncthreads();
    for (int s = 128; s > 0; s >>= 1) {
        if (tid < s) red[tid] += red[tid + s];
        __syncthreads();
    }
    if (tid == 0) {
        float n = sqrtf(red[0]);
        g_invn[pb][p] = 1.f / fmaxf(n, 1e-4f);
    }
}

// ------------------------------------------------------------------
// mask patches (k=4,s=2,pad=1): mm[q] = (sum == 0) ? 1 : 0
// ------------------------------------------------------------------
__global__ void mask_patch_kernel(const float* __restrict__ mask, int pb) {
    int q = blockIdx.x * blockDim.x + threadIdx.x;
    if (q >= LP) return;
    int qi = q >> 6, qj = q & 63;
    float s = 0.f;
    for (int ky = 0; ky < 4; ky++)
        for (int kx = 0; kx < 4; kx++) {
            int yy = 2 * qi - 1 + ky, xx = 2 * qj - 1 + kx;
            if (yy >= 0 && yy < H1N && xx >= 0 && xx < W1N)
                s += mask[yy * W1N + xx];
        }
    g_mm[pb][q] = (s == 0.f) ? 1.f : 0.f;
}

// ------------------------------------------------------------------
// masked softmax over q for each row p; writes fp16 P
// ------------------------------------------------------------------
__global__ void __launch_bounds__(256) softmax_kernel(const float* __restrict__ mask_all, int pb) {
    int p = blockIdx.x;
    int tid = threadIdx.x;
    float map = mask_all[p];
    const float* row = g_S[pb] + (size_t)p * LP;
    const float* mm = g_mm[pb];
    __half* prow = g_P[pb] + (size_t)p * LP;

    float v[16];
    float lmax = -1e30f;
#pragma unroll
    for (int i = 0; i < 16; i++) {
        int q = tid + i * 256;
        float x = row[q] * mm[q] * map;
        v[i] = x;
        lmax = fmaxf(lmax, x);
    }
    __shared__ float red[256];
    red[tid] = lmax;
    __syncthreads();
    for (int s = 128; s > 0; s >>= 1) {
        if (tid < s) red[tid] = fmaxf(red[tid], red[tid + s]);
        __syncthreads();
    }
    float gmax = red[0];
    __syncthreads();

    float lsum = 0.f;
#pragma unroll
    for (int i = 0; i < 16; i++) {
        float e = expf(SCALE_F * (v[i] - gmax));
        v[i] = e;
        lsum += e;
    }
    red[tid] = lsum;
    __syncthreads();
    for (int s = 128; s > 0; s >>= 1) {
        if (tid < s) red[tid] += red[tid + s];
        __syncthreads();
    }
    float inv = 1.f / red[0];
#pragma unroll
    for (int i = 0; i < 16; i++) {
        int q = tid + i * 256;
        float pv = fmaxf(v[i] * inv * mm[q] * map, 1e-8f);
        prow[q] = __float2half_rn(pv);
    }
}

// ------------------------------------------------------------------
// rawT[m][q] -> fp16 (k=4, s=2, pad=1), m = o*16+ky*4+kx
// ------------------------------------------------------------------
__global__ void fill_raw_kernel(const float* __restrict__ x1, int pb) {
    int q = blockIdx.x * blockDim.x + threadIdx.x;
    int m = blockIdx.y;
    int o = m >> 4, kk = m & 15;
    int ky = kk >> 2, kx = kk & 3;
    int qi = q >> 6, qj = q & 63;
    int yy = 2 * qi - 1 + ky, xx = 2 * qj - 1 + kx;
    float v = 0.f;
    if (yy >= 0 && yy < H1N && xx >= 0 && xx < W1N)
        v = x1[(o * H1N + yy) * W1N + xx];
    g_rawh[pb][(size_t)m * LP + q] = __float2half_rn(v);
}

// ------------------------------------------------------------------
// col2im gather: y[o,Y,X] = 0.25 * sum over <=4 entries of cols
// ------------------------------------------------------------------
__global__ void col2im_kernel(int b, int pb) {
    int idx = blockIdx.x * blockDim.x + threadIdx.x;
    int X = idx & 127;
    int Y = (idx >> 7) & 127;
    int o = idx >> 14;
    const float* cols = g_cols[pb];
    float acc = 0.f;
    int ky0 = (Y & 1) ? 0 : 1;
    int kx0 = (X & 1) ? 0 : 1;
#pragma unroll
    for (int t = 0; t < 2; t++) {
        int ky = ky0 + 2 * t;
        int i = (Y + 1 - ky) >> 1;
        if (i < 0 || i >= 64) continue;
#pragma unroll
        for (int u = 0; u < 2; u++) {
            int kx = kx0 + 2 * u;
            int j = (X + 1 - kx) >> 1;
            if (j < 0 || j >= 64) continue;
            acc += cols[(size_t)(o * 16 + ky * 4 + kx) * LP + i * 64 + j];
        }
    }
    g_y[(size_t)b * C1N * H1N * W1N + idx] = acc * 0.25f;
}

// ------------------------------------------------------------------
// final: 4 grouped dilated 3x3 convs (rates 1,2,4,8) + bias + relu
// ------------------------------------------------------------------
__global__ void __launch_bounds__(256) final_conv_kernel(
    const float* __restrict__ w, const float* __restrict__ bias, float* __restrict__ out)
{
    int tile = blockIdx.x;
    int g = blockIdx.y;
    int b = blockIdx.z;
    int r = 1 << g;  // rates 1,2,4,8
    int ty0 = (tile >> 3) * 16, tx0 = (tile & 7) * 16;
    int HW = 16 + 2 * r;
    __shared__ float yt[32 * 32];
    __shared__ float ws[144];
    int tid = threadIdx.x;
    int py = tid >> 4, px = tid & 15;

    float acc[16];
#pragma unroll
    for (int i = 0; i < 16; i++) acc[i] = 0.f;

    const float* yb = g_y + (size_t)b * C1N * H1N * W1N;
    for (int c = 0; c < C1N; c++) {
        for (int idx = tid; idx < HW * HW; idx += 256) {
            int iy = idx / HW, ix = idx % HW;
            int gy = ty0 - r + iy, gx = tx0 - r + ix;
            float v = 0.f;
            if (gy >= 0 && gy < H1N && gx >= 0 && gx < W1N)
                v = yb[(c * H1N + gy) * W1N + gx];
            yt[idx] = v;
        }
        if (tid < 144)
            ws[tid] = w[((g * 16 + tid / 9) * C1N + c) * 9 + tid % 9];
        __syncthreads();
#pragma unroll
        for (int ky = 0; ky < 3; ky++)
#pragma unroll
            for (int kx = 0; kx < 3; kx++) {
                float v = yt[(py + ky * r) * HW + px + kx * r];
#pragma unroll
                for (int oc = 0; oc < 16; oc++)
                    acc[oc] += v * ws[oc * 9 + ky * 3 + kx];
            }
        __syncthreads();
    }
    int Y = ty0 + py, X = tx0 + px;
#pragma unroll
    for (int oc = 0; oc < 16; oc++) {
        float o = acc[oc] + bias[g * 16 + oc];
        out[((size_t)(b * 64 + g * 16 + oc) * H1N + Y) * W1N + X] = fmaxf(o, 0.f);
    }
}

// ------------------------------------------------------------------
extern "C" void kernel_launch(void* const* d_in, const int* in_sizes, int n_in,
                              void* d_out, int out_size) {
    const float* x1       = (const float*)d_in[0];  // [4,128,128,128]
    const float* x2       = (const float*)d_in[1];  // [4,64,64,64]
    const float* mask     = (const float*)d_in[2];  // [4,1,128,128]
    const float* mask_all = (const float*)d_in[3];  // [4,1,64,64]
    const float* conv_w   = (const float*)d_in[4];  // [4,16,128,3,3]
    const float* conv_b   = (const float*)d_in[5];  // [4,16]
    float* out = (float*)d_out;

    static cudaStream_t sx[BATCH - 1] = {};
    static cudaEvent_t evFork, evJoin[BATCH - 1];
    if (!sx[0]) {
        for (int i = 0; i < BATCH - 1; i++) {
            cudaStreamCreateWithFlags(&sx[i], cudaStreamNonBlocking);
            cudaEventCreateWithFlags(&evJoin[i], cudaEventDisableTiming);
        }
        cudaEventCreateWithFlags(&evFork, cudaEventDisableTiming);
    }

    // fork all extra streams from the capture stream
    cudaEventRecord(evFork, 0);
    for (int i = 0; i < BATCH - 1; i++)
        cudaStreamWaitEvent(sx[i], evFork, 0);

    for (int b = 0; b < BATCH; b++) {
        cudaStream_t st = (b == 0) ? (cudaStream_t)0 : sx[b - 1];
        mask_patch_kernel<<<LP / 256, 256, 0, st>>>(mask + (size_t)b * H1N * W1N, b);
        im2col_norm_kernel<<<LP, 256, 0, st>>>(x2 + (size_t)b * C2N * H2N * W2N, b);
        fill_raw_kernel<<<dim3(LP / 256, MRAW), 256, 0, st>>>(x1 + (size_t)b * C1N * H1N * W1N, b);
        gemm1_mma<<<528, 256, 0, st>>>(b);
        softmax_kernel<<<LP, 256, 0, st>>>(mask_all + (size_t)b * LP, b);
        gemm2_mma<<<dim3(32, 16), 256, 0, st>>>(b);
        col2im_kernel<<<(C1N * H1N * W1N) / 256, 256, 0, st>>>(b, b);
    }

    // join all extra streams back into stream 0 before final conv
    for (int i = 0; i < BATCH - 1; i++) {
        cudaEventRecord(evJoin[i], sx[i]);
        cudaStreamWaitEvent(0, evJoin[i], 0);
    }
    final_conv_kernel<<<dim3(64, 4, 4), 256>>>(conv_w, conv_b, out);
}

// round 16
// speedup vs baseline: 1.3179x; 1.0445x over previous
#include <cuda_runtime.h>
#include <cuda_fp16.h>
#include <math.h>
#include <stdint.h>

#define BATCH 4
#define C1N 128
#define H1N 128
#define W1N 128
#define C2N 64
#define H2N 64
#define W2N 64
#define LP 4096          // H2*W2 positions / patches
#define KPATCH 576       // C2 * 3 * 3
#define MRAW 2048        // C1 * 4 * 4
#define SCALE_F 10.0f

// ---- scratch (device globals, one set per batch for 4-way overlap) ----
__device__ __half g_Ah[BATCH][LP * KPATCH];
__device__ __half g_Al[BATCH][LP * KPATCH];
__device__ float  g_invn[BATCH][LP];
__device__ float  g_mm[BATCH][LP];
__device__ float  g_S[BATCH][(size_t)LP * LP];
__device__ __half g_P[BATCH][(size_t)LP * LP];      // compacted softmax [p][j<nqpad]
__device__ __half g_rawh[BATCH][(size_t)MRAW * LP]; // full rawT fp16 [m][q]
__device__ __half g_rawc[BATCH][(size_t)MRAW * LP]; // compacted rawT [m][j<nqpad]
__device__ float  g_cols[BATCH][(size_t)MRAW * LP];
__device__ float  g_y[(size_t)BATCH * C1N * H1N * W1N];
__device__ int    g_idx[BATCH][LP];    // compacted j -> q
__device__ int    g_cpos[BATCH][LP];   // q -> compacted j (valid where mm=1)
__device__ int    g_nq[BATCH];
__device__ int    g_nqpad[BATCH];
__device__ float  g_corr[BATCH][MRAW]; // 1e-8 * sum_{mm=0} raw[m][q]

// ==================================================================
// mma.sync fp16 + ldmatrix + cp.async (base PTX, compiles at compute_103)
// ==================================================================
__device__ __forceinline__ void mma_f16(float d[4], const uint32_t a[4], const uint32_t b[2]) {
    asm volatile(
        "mma.sync.aligned.m16n8k16.row.col.f32.f16.f16.f32 "
        "{%0,%1,%2,%3},{%4,%5,%6,%7},{%8,%9},{%0,%1,%2,%3};"
        : "+f"(d[0]), "+f"(d[1]), "+f"(d[2]), "+f"(d[3])
        : "r"(a[0]), "r"(a[1]), "r"(a[2]), "r"(a[3]), "r"(b[0]), "r"(b[1]));
}
#define LDSM_X4(R, addr) \
    asm volatile("ldmatrix.sync.aligned.m8n8.x4.shared.b16 {%0,%1,%2,%3}, [%4];" \
        : "=r"((R)[0]), "=r"((R)[1]), "=r"((R)[2]), "=r"((R)[3]) : "r"(addr))

__device__ __forceinline__ uint32_t smem_u32(const void* p) {
    uint32_t a;
    asm("{ .reg .u64 t; cvta.to.shared.u64 t, %1; cvt.u32.u64 %0, t; }" : "=r"(a) : "l"(p));
    return a;
}
__device__ __forceinline__ void cp16(uint32_t dst, const void* src) {
    asm volatile(
        "{ .reg .u64 gp; cvta.to.global.u64 gp, %1;"
        " cp.async.ca.shared.global [%0], [gp], 16; }"
        :: "r"(dst), "l"(src) : "memory");
}
#define CP_COMMIT() asm volatile("cp.async.commit_group;" ::: "memory")
#define CP_WAIT0()  asm volatile("cp.async.wait_group 0;" ::: "memory")

#define SSTR1 12   // gemm1 smem row stride in u32 words (8 data + 4 pad), BK=16
#define SSTR2 20   // gemm2 smem row stride in u32 words (16 data + 4 pad), BK=32
#define STG1 (128 * SSTR1)
#define STG2 (128 * SSTR2)

// ==================================================================
// GEMM1 (symmetric): S[p][q] = <A_p, A_q> * invn[q].
// Lower-triangle blocks only; writes tile + transpose. fp16 2-term
// split, 3 MMA terms. K=576, BK=16, 8 warps, 128x128 tile, cp.async
// 2-stage pipeline, 2 CTAs/SM. 528 blocks.
// ==================================================================
__global__ void __launch_bounds__(256, 2) gemm1_mma(int pb) {
    __shared__ uint32_t sm[8 * STG1];
    const int K = KPATCH;
    int t = threadIdx.x;

    int L = blockIdx.x;
    int bx = (int)((sqrtf(8.f * (float)L + 1.f) - 1.f) * 0.5f);
    while ((bx + 1) * (bx + 2) / 2 <= L) bx++;
    while (bx * (bx + 1) / 2 > L) bx--;
    int by = L - bx * (bx + 1) / 2;

    int m0 = by * 128, n0 = bx * 128;
    int wid = t >> 5, lane = t & 31;
    int wm = (wid >> 1) * 32, wn = (wid & 1) * 64;
    int g = lane >> 2, tig = lane & 3;

    const __half* Ah = g_Ah[pb];
    const __half* Al = g_Al[pb];
    const float* invn = g_invn[pb];
    float* S = g_S[pb];

    float acc[2][8][4] = {};

    int lm = t >> 1;
    int lw = (t & 1) * 4;
    const __half* pAh = Ah + (size_t)(m0 + lm) * K + lw * 2;
    const __half* pAl = Al + (size_t)(m0 + lm) * K + lw * 2;
    const __half* pBh = Ah + (size_t)(n0 + lm) * K + lw * 2;
    const __half* pBl = Al + (size_t)(n0 + lm) * K + lw * 2;

    uint32_t smb = smem_u32(sm);
    uint32_t stoff = (uint32_t)(lm * SSTR1 + lw) * 4;
    uint32_t dAh = smb + stoff;
    uint32_t dAl = smb + 2 * STG1 * 4 + stoff;
    uint32_t dBh = smb + 4 * STG1 * 4 + stoff;
    uint32_t dBl = smb + 6 * STG1 * 4 + stoff;
    const uint32_t SGB = STG1 * 4;

    int rowA = lane & 15;
    int koffA = ((lane >> 4) & 1) * 4;
    int rowB = (lane & 7) + ((lane & 16) >> 1);
    int koffB = ((lane & 8) >> 1);
    uint32_t aWh = smb + 4 * ((wm + rowA) * SSTR1 + koffA);
    uint32_t aWl = smb + 2 * STG1 * 4 + 4 * ((wm + rowA) * SSTR1 + koffA);
    uint32_t bWh = smb + 4 * STG1 * 4 + 4 * ((wn + rowB) * SSTR1 + koffB);
    uint32_t bWl = smb + 6 * STG1 * 4 + 4 * ((wn + rowB) * SSTR1 + koffB);

    const int NC = K / 16;
    cp16(dAh, pAh);  cp16(dAl, pAl);  cp16(dBh, pBh);  cp16(dBl, pBl);
    CP_COMMIT();

    for (int ci = 0; ci < NC; ci++) {
        CP_WAIT0();
        __syncthreads();
        uint32_t cur = (uint32_t)(ci & 1) * SGB;
        if (ci + 1 < NC) {
            uint32_t nxt = (uint32_t)((ci + 1) & 1) * SGB;
            int k0 = (ci + 1) * 16;
            cp16(dAh + nxt, pAh + k0);
            cp16(dAl + nxt, pAl + k0);
            cp16(dBh + nxt, pBh + k0);
            cp16(dBl + nxt, pBl + k0);
            CP_COMMIT();
        }
        uint32_t ah[2][4], al[2][4], bh[8][2], bl[8][2];
#pragma unroll
        for (int mt = 0; mt < 2; mt++) {
            uint32_t off = cur + (uint32_t)(mt * 16 * SSTR1) * 4;
            LDSM_X4(ah[mt], aWh + off);
            LDSM_X4(al[mt], aWl + off);
        }
#pragma unroll
        for (int ntp = 0; ntp < 4; ntp++) {
            uint32_t off = cur + (uint32_t)(ntp * 16 * SSTR1) * 4;
            LDSM_X4(&bh[2 * ntp][0], bWh + off);
            LDSM_X4(&bl[2 * ntp][0], bWl + off);
        }
#pragma unroll
        for (int mt = 0; mt < 2; mt++)
#pragma unroll
            for (int nt = 0; nt < 8; nt++) {
                mma_f16(acc[mt][nt], ah[mt], bh[nt]);
                mma_f16(acc[mt][nt], ah[mt], bl[nt]);
                mma_f16(acc[mt][nt], al[mt], bh[nt]);
            }
    }
#pragma unroll
    for (int mt = 0; mt < 2; mt++) {
        int row = m0 + wm + mt * 16 + g;
        float sr0 = __ldg(&invn[row]);
        float sr8 = __ldg(&invn[row + 8]);
#pragma unroll
        for (int nt = 0; nt < 8; nt++) {
            int col = n0 + wn + nt * 8 + 2 * tig;
            float s0 = __ldg(&invn[col]);
            float s1 = __ldg(&invn[col + 1]);
            *(float2*)(S + (size_t)row * LP + col) =
                make_float2(acc[mt][nt][0] * s0, acc[mt][nt][1] * s1);
            *(float2*)(S + (size_t)(row + 8) * LP + col) =
                make_float2(acc[mt][nt][2] * s0, acc[mt][nt][3] * s1);
            S[(size_t)col * LP + row]           = acc[mt][nt][0] * sr0;
            S[(size_t)(col + 1) * LP + row]     = acc[mt][nt][1] * sr0;
            S[(size_t)col * LP + row + 8]       = acc[mt][nt][2] * sr8;
            S[(size_t)(col + 1) * LP + row + 8] = acc[mt][nt][3] * sr8;
        }
    }
}

// ==================================================================
// GEMM2 (compacted K): cols[m][p] = sum_j rawc[m][j] * Pc[p][j] + corr[m]
// K extent = g_nqpad[pb] (multiple of 32, data-dependent, deterministic).
// BK=32, 8 warps, 128x128 tile, cp.async 2-stage, 2 CTAs/SM.
// ==================================================================
__global__ void __launch_bounds__(256, 2) gemm2_mma(int pb) {
    __shared__ uint32_t sm[4 * STG2];
    int t = threadIdx.x;
    int m0 = blockIdx.y * 128, n0 = blockIdx.x * 128;
    int wid = t >> 5, lane = t & 31;
    int wm = (wid >> 1) * 32, wn = (wid & 1) * 64;
    int g = lane >> 2, tig = lane & 3;

    float acc[2][8][4] = {};

    int lm = t >> 1;
    int lw = (t & 1) * 8;
    const __half* pA = g_rawc[pb] + (size_t)(m0 + lm) * LP + lw * 2;
    const __half* pB = g_P[pb]    + (size_t)(n0 + lm) * LP + lw * 2;
    float* cols = g_cols[pb];
    const float* corr = g_corr[pb];

    uint32_t smb = smem_u32(sm);
    uint32_t stoff = (uint32_t)(lm * SSTR2 + lw) * 4;
    uint32_t dA = smb + stoff;
    uint32_t dB = smb + 2 * STG2 * 4 + stoff;
    const uint32_t SGB = STG2 * 4;

    int rowA = lane & 15;
    int koffA = ((lane >> 4) & 1) * 4;
    int rowB = (lane & 7) + ((lane & 16) >> 1);
    int koffB = ((lane & 8) >> 1);
    uint32_t aW = smb + 4 * ((wm + rowA) * SSTR2 + koffA);
    uint32_t bW = smb + 2 * STG2 * 4 + 4 * ((wn + rowB) * SSTR2 + koffB);

    const int NC = g_nqpad[pb] / 32;
    if (NC > 0) {
        cp16(dA, pA);        cp16(dA + 16, pA + 8);
        cp16(dB, pB);        cp16(dB + 16, pB + 8);
        CP_COMMIT();

        for (int ci = 0; ci < NC; ci++) {
            CP_WAIT0();
            __syncthreads();
            uint32_t cur = (uint32_t)(ci & 1) * SGB;
            if (ci + 1 < NC) {
                uint32_t nxt = (uint32_t)((ci + 1) & 1) * SGB;
                int k0 = (ci + 1) * 32;
                cp16(dA + nxt, pA + k0);       cp16(dA + nxt + 16, pA + k0 + 8);
                cp16(dB + nxt, pB + k0);       cp16(dB + nxt + 16, pB + k0 + 8);
                CP_COMMIT();
            }
#pragma unroll
            for (int s = 0; s < 2; s++) {
                uint32_t a[2][4], b[8][2];
#pragma unroll
                for (int mt = 0; mt < 2; mt++) {
                    uint32_t off = cur + (uint32_t)(mt * 16 * SSTR2 + s * 8) * 4;
                    LDSM_X4(a[mt], aW + off);
                }
#pragma unroll
                for (int ntp = 0; ntp < 4; ntp++) {
                    uint32_t off = cur + (uint32_t)(ntp * 16 * SSTR2 + s * 8) * 4;
                    LDSM_X4(&b[2 * ntp][0], bW + off);
                }
#pragma unroll
                for (int mt = 0; mt < 2; mt++)
#pragma unroll
                    for (int nt = 0; nt < 8; nt++)
                        mma_f16(acc[mt][nt], a[mt], b[nt]);
            }
        }
    }
#pragma unroll
    for (int mt = 0; mt < 2; mt++) {
        int row = m0 + wm + mt * 16 + g;
        float c0 = __ldg(&corr[row]);
        float c8 = __ldg(&corr[row + 8]);
#pragma unroll
        for (int nt = 0; nt < 8; nt++) {
            int col = n0 + wn + nt * 8 + 2 * tig;
            *(float2*)(cols + (size_t)row * LP + col) =
                make_float2(acc[mt][nt][0] + c0, acc[mt][nt][1] + c0);
            *(float2*)(cols + (size_t)(row + 8) * LP + col) =
                make_float2(acc[mt][nt][2] + c8, acc[mt][nt][3] + c8);
        }
    }
}

// ------------------------------------------------------------------
// im2col of x2 (k=3,s=1,pad=1) -> fp16 hi/lo split + inverse norms
// ------------------------------------------------------------------
__global__ void im2col_norm_kernel(const float* __restrict__ x2, int pb) {
    int p = blockIdx.x;
    int pi = p >> 6, pj = p & 63;
    int tid = threadIdx.x;
    float ss = 0.f;
    for (int k = tid; k < KPATCH; k += 256) {
        int c = k / 9, ki = k % 9;
        int ky = ki / 3, kx = ki % 3;
        int yy = pi - 1 + ky, xx = pj - 1 + kx;
        float v = 0.f;
        if (yy >= 0 && yy < H2N && xx >= 0 && xx < W2N)
            v = x2[(c * H2N + yy) * W2N + xx];
        __half h = __float2half_rn(v);
        g_Ah[pb][p * KPATCH + k] = h;
        g_Al[pb][p * KPATCH + k] = __float2half_rn(v - __half2float(h));
        ss += v * v;
    }
    __shared__ float red[256];
    red[tid] = ss;
    __syncthreads();
    for (int s = 128; s > 0; s >>= 1) {
        if (tid < s) red[tid] += red[tid + s];
        __syncthreads();
    }
    if (tid == 0) {
        float n = sqrtf(red[0]);
        g_invn[pb][p] = 1.f / fmaxf(n, 1e-4f);
    }
}

// ------------------------------------------------------------------
// mask patches (k=4,s=2,pad=1): mm[q] = (sum == 0) ? 1 : 0
// ------------------------------------------------------------------
__global__ void mask_patch_kernel(const float* __restrict__ mask, int pb) {
    int q = blockIdx.x * blockDim.x + threadIdx.x;
    if (q >= LP) return;
    int qi = q >> 6, qj = q & 63;
    float s = 0.f;
    for (int ky = 0; ky < 4; ky++)
        for (int kx = 0; kx < 4; kx++) {
            int yy = 2 * qi - 1 + ky, xx = 2 * qj - 1 + kx;
            if (yy >= 0 && yy < H1N && xx >= 0 && xx < W1N)
                s += mask[yy * W1N + xx];
        }
    g_mm[pb][q] = (s == 0.f) ? 1.f : 0.f;
}

// ------------------------------------------------------------------
// scan: build compacted index list of q with mm=1. 1 block, 1024 thr.
// ------------------------------------------------------------------
__global__ void __launch_bounds__(1024) scan_kernel(int pb) {
    __shared__ int ssum[1024];
    int tid = threadIdx.x;
    const float* mm = g_mm[pb];
    int loc[4];
    int s = 0;
#pragma unroll
    for (int i = 0; i < 4; i++) {
        int q = tid * 4 + i;
        loc[i] = s;
        s += (mm[q] > 0.f) ? 1 : 0;
    }
    ssum[tid] = s;
    __syncthreads();
    for (int off = 1; off < 1024; off <<= 1) {
        int v = 0;
        if (tid >= off) v = ssum[tid - off];
        __syncthreads();
        if (tid >= off) ssum[tid] += v;
        __syncthreads();
    }
    int base = (tid > 0) ? ssum[tid - 1] : 0;
#pragma unroll
    for (int i = 0; i < 4; i++) {
        int q = tid * 4 + i;
        if (mm[q] > 0.f) {
            int pos = base + loc[i];
            g_idx[pb][pos] = q;
            g_cpos[pb][q] = pos;
        }
    }
    if (tid == 0) {
        int nq = ssum[1023];
        g_nq[pb] = nq;
        g_nqpad[pb] = ((nq + 31) / 32) * 32;
    }
}

// ------------------------------------------------------------------
// masked softmax over q for each row p; writes COMPACTED fp16 P
// ------------------------------------------------------------------
__global__ void __launch_bounds__(256) softmax_kernel(const float* __restrict__ mask_all, int pb) {
    int p = blockIdx.x;
    int tid = threadIdx.x;
    float map = mask_all[p];
    const float* row = g_S[pb] + (size_t)p * LP;
    const float* mm = g_mm[pb];
    const int* cpos = g_cpos[pb];
    __half* prow = g_P[pb] + (size_t)p * LP;

    float v[16];
    float lmax = -1e30f;
#pragma unroll
    for (int i = 0; i < 16; i++) {
        int q = tid + i * 256;
        float x = row[q] * mm[q] * map;
        v[i] = x;
        lmax = fmaxf(lmax, x);
    }
    __shared__ float red[256];
    red[tid] = lmax;
    __syncthreads();
    for (int s = 128; s > 0; s >>= 1) {
        if (tid < s) red[tid] = fmaxf(red[tid], red[tid + s]);
        __syncthreads();
    }
    float gmax = red[0];
    __syncthreads();

    float lsum = 0.f;
#pragma unroll
    for (int i = 0; i < 16; i++) {
        float e = expf(SCALE_F * (v[i] - gmax));
        v[i] = e;
        lsum += e;
    }
    red[tid] = lsum;
    __syncthreads();
    for (int s = 128; s > 0; s >>= 1) {
        if (tid < s) red[tid] += red[tid + s];
        __syncthreads();
    }
    float inv = 1.f / red[0];
    // compacted write: only mm=1 entries land in P (others are constant 1e-8,
    // folded into g_corr)
#pragma unroll
    for (int i = 0; i < 16; i++) {
        int q = tid + i * 256;
        if (mm[q] > 0.f) {
            float pv = fmaxf(v[i] * inv * map, 1e-8f);
            prow[cpos[q]] = __float2half_rn(pv);
        }
    }
    // zero-pad [nq, nqpad)
    int nq = g_nq[pb];
    int pad = g_nqpad[pb] - nq;
    if (tid < pad) prow[nq + tid] = __float2half_rn(0.f);
}

// ------------------------------------------------------------------
// rawT[m][q] -> fp16 (k=4, s=2, pad=1), m = o*16+ky*4+kx
// ------------------------------------------------------------------
__global__ void fill_raw_kernel(const float* __restrict__ x1, int pb) {
    int q = blockIdx.x * blockDim.x + threadIdx.x;
    int m = blockIdx.y;
    int o = m >> 4, kk = m & 15;
    int ky = kk >> 2, kx = kk & 3;
    int qi = q >> 6, qj = q & 63;
    int yy = 2 * qi - 1 + ky, xx = 2 * qj - 1 + kx;
    float v = 0.f;
    if (yy >= 0 && yy < H1N && xx >= 0 && xx < W1N)
        v = x1[(o * H1N + yy) * W1N + xx];
    g_rawh[pb][(size_t)m * LP + q] = __float2half_rn(v);
}

// ------------------------------------------------------------------
// comp_raw: per row m — gather compacted rawc and compute
// corr[m] = 1e-8 * sum_{mm=0} raw[m][q]. One block per m.
// ------------------------------------------------------------------
__global__ void __launch_bounds__(256) comp_raw_kernel(int pb) {
    int m = blockIdx.x;
    int tid = threadIdx.x;
    const __half* raw = g_rawh[pb] + (size_t)m * LP;
    const float* mm = g_mm[pb];
    const int* idx = g_idx[pb];
    __half* rawc = g_rawc[pb] + (size_t)m * LP;
    int nq = g_nq[pb];
    int nqpad = g_nqpad[pb];

    // gather compacted columns (+ zero pad)
    for (int j = tid; j < nqpad; j += 256)
        rawc[j] = (j < nq) ? raw[idx[j]] : __float2half_rn(0.f);

    // reduce sum over mm==0 entries
    float s = 0.f;
    for (int q = tid; q < LP; q += 256)
        if (mm[q] == 0.f) s += __half2float(raw[q]);
    __shared__ float red[256];
    red[tid] = s;
    __syncthreads();
    for (int st = 128; st > 0; st >>= 1) {
        if (tid < st) red[tid] += red[tid + st];
        __syncthreads();
    }
    if (tid == 0) g_corr[pb][m] = 1e-8f * red[0];
}

// ------------------------------------------------------------------
// col2im gather: y[o,Y,X] = 0.25 * sum over <=4 entries of cols
// ------------------------------------------------------------------
__global__ void col2im_kernel(int b, int pb) {
    int idx = blockIdx.x * blockDim.x + threadIdx.x;
    int X = idx & 127;
    int Y = (idx >> 7) & 127;
    int o = idx >> 14;
    const float* cols = g_cols[pb];
    float acc = 0.f;
    int ky0 = (Y & 1) ? 0 : 1;
    int kx0 = (X & 1) ? 0 : 1;
#pragma unroll
    for (int t = 0; t < 2; t++) {
        int ky = ky0 + 2 * t;
        int i = (Y + 1 - ky) >> 1;
        if (i < 0 || i >= 64) continue;
#pragma unroll
        for (int u = 0; u < 2; u++) {
            int kx = kx0 + 2 * u;
            int j = (X + 1 - kx) >> 1;
            if (j < 0 || j >= 64) continue;
            acc += cols[(size_t)(o * 16 + ky * 4 + kx) * LP + i * 64 + j];
        }
    }
    g_y[(size_t)b * C1N * H1N * W1N + idx] = acc * 0.25f;
}

// ------------------------------------------------------------------
// final: 4 grouped dilated 3x3 convs (rates 1,2,4,8) + bias + relu
// ------------------------------------------------------------------
__global__ void __launch_bounds__(256) final_conv_kernel(
    const float* __restrict__ w, const float* __restrict__ bias, float* __restrict__ out)
{
    int tile = blockIdx.x;
    int g = blockIdx.y;
    int b = blockIdx.z;
    int r = 1 << g;  // rates 1,2,4,8
    int ty0 = (tile >> 3) * 16, tx0 = (tile & 7) * 16;
    int HW = 16 + 2 * r;
    __shared__ float yt[32 * 32];
    __shared__ float ws[144];
    int tid = threadIdx.x;
    int py = tid >> 4, px = tid & 15;

    float acc[16];
#pragma unroll
    for (int i = 0; i < 16; i++) acc[i] = 0.f;

    const float* yb = g_y + (size_t)b * C1N * H1N * W1N;
    for (int c = 0; c < C1N; c++) {
        for (int idx = tid; idx < HW * HW; idx += 256) {
            int iy = idx / HW, ix = idx % HW;
            int gy = ty0 - r + iy, gx = tx0 - r + ix;
            float v = 0.f;
            if (gy >= 0 && gy < H1N && gx >= 0 && gx < W1N)
                v = yb[(c * H1N + gy) * W1N + gx];
            yt[idx] = v;
        }
        if (tid < 144)
            ws[tid] = w[((g * 16 + tid / 9) * C1N + c) * 9 + tid % 9];
        __syncthreads();
#pragma unroll
        for (int ky = 0; ky < 3; ky++)
#pragma unroll
            for (int kx = 0; kx < 3; kx++) {
                float v = yt[(py + ky * r) * HW + px + kx * r];
#pragma unroll
                for (int oc = 0; oc < 16; oc++)
                    acc[oc] += v * ws[oc * 9 + ky * 3 + kx];
            }
        __syncthreads();
    }
    int Y = ty0 + py, X = tx0 + px;
#pragma unroll
    for (int oc = 0; oc < 16; oc++) {
        float o = acc[oc] + bias[g * 16 + oc];
        out[((size_t)(b * 64 + g * 16 + oc) * H1N + Y) * W1N + X] = fmaxf(o, 0.f);
    }
}

// ------------------------------------------------------------------
extern "C" void kernel_launch(void* const* d_in, const int* in_sizes, int n_in,
                              void* d_out, int out_size) {
    const float* x1       = (const float*)d_in[0];  // [4,128,128,128]
    const float* x2       = (const float*)d_in[1];  // [4,64,64,64]
    const float* mask     = (const float*)d_in[2];  // [4,1,128,128]
    const float* mask_all = (const float*)d_in[3];  // [4,1,64,64]
    const float* conv_w   = (const float*)d_in[4];  // [4,16,128,3,3]
    const float* conv_b   = (const float*)d_in[5];  // [4,16]
    float* out = (float*)d_out;

    static cudaStream_t sx[BATCH - 1] = {};
    static cudaEvent_t evFork, evJoin[BATCH - 1];
    if (!sx[0]) {
        for (int i = 0; i < BATCH - 1; i++) {
            cudaStreamCreateWithFlags(&sx[i], cudaStreamNonBlocking);
            cudaEventCreateWithFlags(&evJoin[i], cudaEventDisableTiming);
        }
        cudaEventCreateWithFlags(&evFork, cudaEventDisableTiming);
    }

    // fork all extra streams from the capture stream
    cudaEventRecord(evFork, 0);
    for (int i = 0; i < BATCH - 1; i++)
        cudaStreamWaitEvent(sx[i], evFork, 0);

    for (int b = 0; b < BATCH; b++) {
        cudaStream_t st = (b == 0) ? (cudaStream_t)0 : sx[b - 1];
        mask_patch_kernel<<<LP / 256, 256, 0, st>>>(mask + (size_t)b * H1N * W1N, b);
        scan_kernel<<<1, 1024, 0, st>>>(b);
        im2col_norm_kernel<<<LP, 256, 0, st>>>(x2 + (size_t)b * C2N * H2N * W2N, b);
        fill_raw_kernel<<<dim3(LP / 256, MRAW), 256, 0, st>>>(x1 + (size_t)b * C1N * H1N * W1N, b);
        comp_raw_kernel<<<MRAW, 256, 0, st>>>(b);
        gemm1_mma<<<528, 256, 0, st>>>(b);
        softmax_kernel<<<LP, 256, 0, st>>>(mask_all + (size_t)b * LP, b);
        gemm2_mma<<<dim3(32, 16), 256, 0, st>>>(b);
        col2im_kernel<<<(C1N * H1N * W1N) / 256, 256, 0, st>>>(b, b);
    }

    // join all extra streams back into stream 0 before final conv
    for (int i = 0; i < BATCH - 1; i++) {
        cudaEventRecord(evJoin[i], sx[i]);
        cudaStreamWaitEvent(0, evJoin[i], 0);
    }
    final_conv_kernel<<<dim3(64, 4, 4), 256>>>(conv_w, conv_b, out);
}